// round 8
// baseline (speedup 1.0000x reference)
#include <cuda_runtime.h>
#include <cuda_fp16.h>
#include <cstdint>

#define BATCH 32
#define VLEN  4096
#define HDIM  1024

// ---------------- device scratch ----------------
__device__ float g_qb[BATCH * HDIM];
__device__ float g_score[BATCH * VLEN];
__device__ __align__(16) __half g_wk[HDIM * HDIM];
__device__ __align__(16) __half g_key16[(size_t)BATCH * VLEN * HDIM];
__device__ float g_ctx_part[8 * BATCH * HDIM];   // v-split context partials

// ---------------- helpers ----------------
__device__ __forceinline__ uint32_t smem_u32(const void* p) {
    uint32_t a;
    asm("{ .reg .u64 t; cvta.to.shared.u64 t, %1; cvt.u32.u64 %0, t; }" : "=r"(a) : "l"(p));
    return a;
}
__device__ __forceinline__ void cp16(uint32_t saddr, const void* g) {
    asm volatile("cp.async.cg.shared.global [%0], [%1], 16;" :: "r"(saddr), "l"(g) : "memory");
}
#define CP_COMMIT()  asm volatile("cp.async.commit_group;" ::: "memory")
#define CP_WAIT(N)   asm volatile("cp.async.wait_group %0;" :: "n"(N) : "memory")

__device__ __forceinline__ void ldsm4(uint32_t* r, uint32_t addr) {
    asm volatile("ldmatrix.sync.aligned.m8n8.x4.shared.b16 {%0,%1,%2,%3}, [%4];"
                 : "=r"(r[0]), "=r"(r[1]), "=r"(r[2]), "=r"(r[3]) : "r"(addr));
}
__device__ __forceinline__ void mma_f16(float* d, const uint32_t* a, uint32_t b0, uint32_t b1) {
    asm volatile("mma.sync.aligned.m16n8k16.row.col.f32.f16.f16.f32 "
                 "{%0,%1,%2,%3}, {%4,%5,%6,%7}, {%8,%9}, {%0,%1,%2,%3};"
                 : "+f"(d[0]), "+f"(d[1]), "+f"(d[2]), "+f"(d[3])
                 : "r"(a[0]), "r"(a[1]), "r"(a[2]), "r"(a[3]), "r"(b0), "r"(b1));
}
__device__ __forceinline__ uint32_t pkh(float a, float b) {
    __half2 h = __floats2half2_rn(a, b);
    return *reinterpret_cast<uint32_t*>(&h);
}
// fast tanh: 1 - 2/(exp(2x)+1); MUFU-based, rel err ~1e-6
__device__ __forceinline__ float ftanh(float x) {
    float e = __expf(2.0f * x);
    return 1.0f - __fdividef(2.0f, e + 1.0f);
}

// ---------------- SMEM layout (bytes) ----------------
// K-chunk 32 fp16 = 64 B per row, pitch 80 B.
// per stage: [A 128*80 = 10240][B 256*80 = 20480] = 30720; 4 stages.
#define PITCH    80
#define OFF_B    10240
#define BUFSZ    30720
#define NSTAGE   4
#define SM_QB    (NSTAGE * BUFSZ)     // 122880, 1024 floats
#define SM_WS    (SM_QB + 4096)       // 126976
#define SM_RED   (SM_WS + 4096)       // 131072
#define SM_TOTAL (SM_RED + 2048)      // 133120

// ---------------------------------------------------------------------------
// Kernel 1: qb[b][o] = bias[o] + sum_h Wq[o][h] * query[b][h]
// ---------------------------------------------------------------------------
__global__ void qb_kernel(const float* __restrict__ query,
                          const float* __restrict__ Wq,
                          const float* __restrict__ bias) {
    int w    = (blockIdx.x * blockDim.x + threadIdx.x) >> 5;
    int lane = threadIdx.x & 31;
    int b = w / HDIM;
    int o = w % HDIM;
    const float* wrow = Wq + (size_t)o * HDIM;
    const float* qrow = query + (size_t)b * HDIM;
    float s = 0.0f;
#pragma unroll 8
    for (int h = lane; h < HDIM; h += 32) s += wrow[h] * qrow[h];
#pragma unroll
    for (int off = 16; off; off >>= 1) s += __shfl_xor_sync(0xffffffffu, s, off);
    if (lane == 0) g_qb[w] = s + bias[o];
}

// ---------------------------------------------------------------------------
// Kernel 1b: convert Wk to fp16
// ---------------------------------------------------------------------------
__global__ void wk_conv_kernel(const float* __restrict__ Wk) {
    int i = (blockIdx.x * 256 + threadIdx.x) * 4;
    float4 w = *reinterpret_cast<const float4*>(Wk + i);
    *reinterpret_cast<uint2*>(g_wk + i) = make_uint2(pkh(w.x, w.y), pkh(w.z, w.w));
}

// ---------------------------------------------------------------------------
// Kernel 1c: convert key to fp16 (bandwidth-bound pre-pass)
// ---------------------------------------------------------------------------
__global__ void key_conv_kernel(const float* __restrict__ key) {
    const size_t i = ((size_t)blockIdx.x * 256 + threadIdx.x) * 8;
    const float4 a = *reinterpret_cast<const float4*>(key + i);
    const float4 b = *reinterpret_cast<const float4*>(key + i + 4);
    *reinterpret_cast<uint4*>(g_key16 + i) =
        make_uint4(pkh(a.x, a.y), pkh(a.z, a.w), pkh(b.x, b.y), pkh(b.z, b.w));
}

// ---------------------------------------------------------------------------
// Kernel 2: score GEMM, 4-stage cp.async pipeline, fp16 MMA, fp32 accum.
// Block: 128 v-rows x 256 o-cols per pass, 4 passes. K-chunk 32.
// ---------------------------------------------------------------------------
__global__ void __launch_bounds__(256, 1)
score_kernel(const float* __restrict__ Ws) {
    extern __shared__ __align__(16) char smem[];
    const uint32_t sb = smem_u32(smem);
    const int tid  = threadIdx.x;
    const int lane = tid & 31;
    const int wid  = tid >> 5;
    const int wy   = wid >> 2;   // 0..1 : M group (64 rows)
    const int wx   = wid & 3;    // 0..3 : N group (64 cols)
    const int b    = blockIdx.y;
    const int v0   = blockIdx.x * 128;

    float* qbs = reinterpret_cast<float*>(smem + SM_QB);
    float* wss = reinterpret_cast<float*>(smem + SM_WS);
#pragma unroll
    for (int i = 0; i < 4; i++) {
        qbs[tid + i * 256] = g_qb[b * HDIM + tid + i * 256];
        wss[tid + i * 256] = Ws[tid + i * 256];
    }

    const __half* keyb = g_key16 + ((size_t)b * VLEN + v0) * HDIM;

    // cp.async mappings
    const int arow = tid >> 1;           // 0..127
    const int aseg = (tid & 1) * 2;      // {0,2}; 16B segs
    const int wn   = tid;                // Wk row 0..255

    const uint32_t aoff  = (uint32_t)((lane & 15) * PITCH + (lane >> 4) * 16);
    const uint32_t Abase = sb + (uint32_t)(wy * 64 * PITCH) + aoff;
    const uint32_t Bbase = sb + OFF_B + (uint32_t)(wx * 64 * PITCH) + aoff;

    float d[4][8][4];
#pragma unroll
    for (int mt = 0; mt < 4; mt++)
#pragma unroll
        for (int j = 0; j < 8; j++)
#pragma unroll
            for (int q = 0; q < 4; q++) d[mt][j][q] = 0.0f;
    float part[8];
#pragma unroll
    for (int i = 0; i < 8; i++) part[i] = 0.0f;

    // issue loads of chunk n into stage buffer s
    auto issue_chunk = [&](int n, int s) {
        const int h0 = (n & 31) * 32;
        const int o0 = (n >> 5) * 256;
        const uint32_t bb = sb + (uint32_t)s * BUFSZ;
        cp16(bb + arow * PITCH + aseg * 16,
             keyb + (size_t)arow * HDIM + h0 + aseg * 8);
        cp16(bb + arow * PITCH + (aseg + 1) * 16,
             keyb + (size_t)arow * HDIM + h0 + (aseg + 1) * 8);
#pragma unroll
        for (int c = 0; c < 4; c++)
            cp16(bb + OFF_B + wn * PITCH + c * 16,
                 g_wk + (size_t)(o0 + wn) * HDIM + h0 + c * 8);
        CP_COMMIT();
    };

    // ---- prologue: stages 0..2 in flight ----
    issue_chunk(0, 0);
    issue_chunk(1, 1);
    issue_chunk(2, 2);

    for (int gc = 0; gc < 128; gc++) {
        // wait until chunk gc has landed (keep up to 2 younger groups in flight)
        if (gc <= 125)      { CP_WAIT(2); }
        else if (gc == 126) { CP_WAIT(1); }
        else                { CP_WAIT(0); }
        __syncthreads();   // chunk gc visible to all; all warps done with chunk gc-1

        // issue chunk gc+3 into the buffer chunk gc-1 just vacated
        if (gc < 125) issue_chunk(gc + 3, (gc + 3) & (NSTAGE - 1));

        // ---- compute chunk gc ----
        {
            const uint32_t abuf = Abase + (uint32_t)(gc & (NSTAGE - 1)) * BUFSZ;
            const uint32_t bbuf = Bbase + (uint32_t)(gc & (NSTAGE - 1)) * BUFSZ;
#pragma unroll
            for (int ks = 0; ks < 2; ks++) {
                uint32_t Bh[4][4];
#pragma unroll
                for (int jj = 0; jj < 4; jj++)
                    ldsm4(Bh[jj], bbuf + jj * (16 * PITCH) + ks * 32);
#pragma unroll
                for (int mt = 0; mt < 4; mt++) {
                    uint32_t Ah[4];
                    ldsm4(Ah, abuf + mt * (16 * PITCH) + ks * 32);
#pragma unroll
                    for (int jj = 0; jj < 4; jj++) {
#pragma unroll
                        for (int h = 0; h < 2; h++)
                            mma_f16(d[mt][jj * 2 + h], Ah, Bh[jj][h], Bh[jj][2 + h]);
                    }
                }
            }
        }

        // ---- end of pass: tanh + Ws reduction, reset accumulators ----
        if ((gc & 31) == 31) {
            const int o0 = (gc >> 5) * 256;
            const int cb = o0 + wx * 64 + (lane & 3) * 2;
#pragma unroll
            for (int mt = 0; mt < 4; mt++) {
#pragma unroll
                for (int j = 0; j < 8; j++) {
                    const int o = cb + j * 8;
                    const float w0 = wss[o], w1 = wss[o + 1];
                    const float q0 = qbs[o], q1 = qbs[o + 1];
                    part[mt * 2 + 0] += w0 * ftanh(d[mt][j][0] + q0) + w1 * ftanh(d[mt][j][1] + q1);
                    part[mt * 2 + 1] += w0 * ftanh(d[mt][j][2] + q0) + w1 * ftanh(d[mt][j][3] + q1);
                    d[mt][j][0] = 0.0f; d[mt][j][1] = 0.0f;
                    d[mt][j][2] = 0.0f; d[mt][j][3] = 0.0f;
                }
            }
        }
    }

    // ---- cross-thread reduction ----
#pragma unroll
    for (int i = 0; i < 8; i++) {
        part[i] += __shfl_xor_sync(0xffffffffu, part[i], 1);
        part[i] += __shfl_xor_sync(0xffffffffu, part[i], 2);
    }
    float* red = reinterpret_cast<float*>(smem + SM_RED);
    if ((lane & 3) == 0) {
        const int r0 = wy * 64 + (lane >> 2);
#pragma unroll
        for (int mt = 0; mt < 4; mt++) {
            red[wx * 128 + r0 + mt * 16]     = part[mt * 2 + 0];
            red[wx * 128 + r0 + mt * 16 + 8] = part[mt * 2 + 1];
        }
    }
    __syncthreads();
    if (tid < 128) {
        const float s = red[tid] + red[128 + tid] + red[256 + tid] + red[384 + tid];
        g_score[b * VLEN + v0 + tid] = s;
    }
}

// ---------------------------------------------------------------------------
// Kernel 3: softmax over V=4096 per batch
// ---------------------------------------------------------------------------
__global__ void softmax_kernel(float* __restrict__ attn_out) {
    __shared__ float red[256];
    const int b = blockIdx.x;
    const int t = threadIdx.x;
    const float* s = g_score + b * VLEN;

    float local[16];
    float mx = -1e30f;
#pragma unroll
    for (int i = 0; i < 16; i++) {
        local[i] = s[t + i * 256];
        mx = fmaxf(mx, local[i]);
    }
    red[t] = mx;
    __syncthreads();
    for (int o = 128; o; o >>= 1) {
        if (t < o) red[t] = fmaxf(red[t], red[t + o]);
        __syncthreads();
    }
    mx = red[0];
    __syncthreads();

    float sum = 0.0f;
#pragma unroll
    for (int i = 0; i < 16; i++) {
        local[i] = expf(local[i] - mx);
        sum += local[i];
    }
    red[t] = sum;
    __syncthreads();
    for (int o = 128; o; o >>= 1) {
        if (t < o) red[t] += red[t + o];
        __syncthreads();
    }
    const float inv = 1.0f / red[0];
#pragma unroll
    for (int i = 0; i < 16; i++) attn_out[b * VLEN + t + i * 256] = local[i] * inv;
}

// ---------------------------------------------------------------------------
// Kernel 4a: context partials with v-split (512 blocks for full-chip MLP)
// ---------------------------------------------------------------------------
__global__ void context_part_kernel(const float* __restrict__ value,
                                    const float* __restrict__ attn) {
    __shared__ float a_s[512];
    const int hc = blockIdx.x, b = blockIdx.y, vs = blockIdx.z;
    const int v0 = vs * 512;
    const float* ap = attn + b * VLEN + v0;
    for (int i = threadIdx.x; i < 512; i += 128) a_s[i] = ap[i];
    __syncthreads();

    const int h = hc * 512 + threadIdx.x * 4;
    const float* vp = value + ((size_t)b * VLEN + v0) * HDIM + h;
    float ax = 0.f, ay = 0.f, az = 0.f, aw = 0.f;
    for (int v = 0; v < 512; v += 8) {
#pragma unroll
        for (int j = 0; j < 8; j++) {
            const float4 x = *reinterpret_cast<const float4*>(vp + (size_t)(v + j) * HDIM);
            const float a = a_s[v + j];
            ax += a * x.x; ay += a * x.y; az += a * x.z; aw += a * x.w;
        }
    }
    *reinterpret_cast<float4*>(g_ctx_part + ((size_t)vs * BATCH + b) * HDIM + h) =
        make_float4(ax, ay, az, aw);
}

// Kernel 4b: reduce 8 partials
__global__ void context_reduce_kernel(float* __restrict__ ctx) {
    const int i = blockIdx.x * 256 + threadIdx.x;
    float s = 0.0f;
#pragma unroll
    for (int vs = 0; vs < 8; vs++) s += g_ctx_part[vs * BATCH * HDIM + i];
    ctx[i] = s;
}

// ---------------------------------------------------------------------------
// Launch. Inputs: query, key, value, Wq, Wk, bias, Ws, bs.
// Output: context (32*1024) then attn (32*4096).
// ---------------------------------------------------------------------------
extern "C" void kernel_launch(void* const* d_in, const int* in_sizes, int n_in,
                              void* d_out, int out_size) {
    const float* query = (const float*)d_in[0];
    const float* key   = (const float*)d_in[1];
    const float* value = (const float*)d_in[2];
    const float* Wq    = (const float*)d_in[3];
    const float* Wk    = (const float*)d_in[4];
    const float* bias  = (const float*)d_in[5];
    const float* Ws    = (const float*)d_in[6];

    float* out  = (float*)d_out;
    float* ctx  = out;                    // (B, 1, H)
    float* attn = out + BATCH * HDIM;     // (B, V)

    cudaFuncSetAttribute(score_kernel, cudaFuncAttributeMaxDynamicSharedMemorySize, SM_TOTAL);

    qb_kernel<<<(BATCH * HDIM * 32) / 256, 256>>>(query, Wq, bias);
    wk_conv_kernel<<<(HDIM * HDIM) / (256 * 4), 256>>>(Wk);
    key_conv_kernel<<<(int)(((size_t)BATCH * VLEN * HDIM) / (256 * 8)), 256>>>(key);
    score_kernel<<<dim3(VLEN / 128, BATCH), 256, SM_TOTAL>>>(Ws);
    softmax_kernel<<<BATCH, 256>>>(attn);
    context_part_kernel<<<dim3(2, BATCH, 8), 128>>>(value, attn);
    context_reduce_kernel<<<(BATCH * HDIM) / 256, 256>>>(ctx);
}

// round 9
// speedup vs baseline: 1.0949x; 1.0949x over previous
#include <cuda_runtime.h>
#include <cuda_fp16.h>
#include <cstdint>

#define BATCH 32
#define VLEN  4096
#define HDIM  1024

// ---------------- device scratch ----------------
__device__ float g_qb[BATCH * HDIM];
__device__ float g_score[BATCH * VLEN];
__device__ __align__(16) __half g_wk[HDIM * HDIM];
__device__ __align__(16) __half g_key16[(size_t)BATCH * VLEN * HDIM];
__device__ float g_ctx_part[8 * BATCH * HDIM];   // v-split context partials

// ---------------- helpers ----------------
__device__ __forceinline__ uint32_t smem_u32(const void* p) {
    uint32_t a;
    asm("{ .reg .u64 t; cvta.to.shared.u64 t, %1; cvt.u32.u64 %0, t; }" : "=r"(a) : "l"(p));
    return a;
}
__device__ __forceinline__ void cp16(uint32_t saddr, const void* g) {
    asm volatile("cp.async.cg.shared.global [%0], [%1], 16;" :: "r"(saddr), "l"(g) : "memory");
}
#define CP_COMMIT()  asm volatile("cp.async.commit_group;" ::: "memory")
#define CP_WAIT(N)   asm volatile("cp.async.wait_group %0;" :: "n"(N) : "memory")

__device__ __forceinline__ void ldsm4(uint32_t* r, uint32_t addr) {
    asm volatile("ldmatrix.sync.aligned.m8n8.x4.shared.b16 {%0,%1,%2,%3}, [%4];"
                 : "=r"(r[0]), "=r"(r[1]), "=r"(r[2]), "=r"(r[3]) : "r"(addr));
}
__device__ __forceinline__ void mma_f16(float* d, const uint32_t* a, uint32_t b0, uint32_t b1) {
    asm volatile("mma.sync.aligned.m16n8k16.row.col.f32.f16.f16.f32 "
                 "{%0,%1,%2,%3}, {%4,%5,%6,%7}, {%8,%9}, {%0,%1,%2,%3};"
                 : "+f"(d[0]), "+f"(d[1]), "+f"(d[2]), "+f"(d[3])
                 : "r"(a[0]), "r"(a[1]), "r"(a[2]), "r"(a[3]), "r"(b0), "r"(b1));
}
__device__ __forceinline__ uint32_t pkh(float a, float b) {
    __half2 h = __floats2half2_rn(a, b);
    return *reinterpret_cast<uint32_t*>(&h);
}
// fast tanh: 1 - 2/(exp(2x)+1); MUFU-based, rel err ~1e-6
__device__ __forceinline__ float ftanh(float x) {
    float e = __expf(2.0f * x);
    return 1.0f - __fdividef(2.0f, e + 1.0f);
}

// ---------------- SMEM layout (bytes) ----------------
// K-chunk 32 fp16 = 64 B per row, pitch 80 B. N-tile 128.
// per stage: [A 128*80 = 10240][B 128*80 = 10240] = 20480; 3 stages.
#define PITCH    80
#define OFF_B    10240
#define BUFSZ    20480
#define NSTAGE   3
#define SM_QB    (NSTAGE * BUFSZ)     // 61440, 1024 floats
#define SM_WS    (SM_QB + 4096)       // 65536
#define SM_RED   (SM_WS + 4096)       // 69632
#define SM_TOTAL (SM_RED + 2048)      // 71680  (x2 CTAs = 140 KB/SM)

// ---------------------------------------------------------------------------
// Kernel 1: qb[b][o] = bias[o] + sum_h Wq[o][h] * query[b][h]
// ---------------------------------------------------------------------------
__global__ void qb_kernel(const float* __restrict__ query,
                          const float* __restrict__ Wq,
                          const float* __restrict__ bias) {
    int w    = (blockIdx.x * blockDim.x + threadIdx.x) >> 5;
    int lane = threadIdx.x & 31;
    int b = w / HDIM;
    int o = w % HDIM;
    const float* wrow = Wq + (size_t)o * HDIM;
    const float* qrow = query + (size_t)b * HDIM;
    float s = 0.0f;
#pragma unroll 8
    for (int h = lane; h < HDIM; h += 32) s += wrow[h] * qrow[h];
#pragma unroll
    for (int off = 16; off; off >>= 1) s += __shfl_xor_sync(0xffffffffu, s, off);
    if (lane == 0) g_qb[w] = s + bias[o];
}

// ---------------------------------------------------------------------------
// Kernel 1b: convert Wk to fp16
// ---------------------------------------------------------------------------
__global__ void wk_conv_kernel(const float* __restrict__ Wk) {
    int i = (blockIdx.x * 256 + threadIdx.x) * 4;
    float4 w = *reinterpret_cast<const float4*>(Wk + i);
    *reinterpret_cast<uint2*>(g_wk + i) = make_uint2(pkh(w.x, w.y), pkh(w.z, w.w));
}

// ---------------------------------------------------------------------------
// Kernel 1c: convert key to fp16 (bandwidth-bound pre-pass)
// ---------------------------------------------------------------------------
__global__ void key_conv_kernel(const float* __restrict__ key) {
    const size_t i = ((size_t)blockIdx.x * 256 + threadIdx.x) * 8;
    const float4 a = *reinterpret_cast<const float4*>(key + i);
    const float4 b = *reinterpret_cast<const float4*>(key + i + 4);
    *reinterpret_cast<uint4*>(g_key16 + i) =
        make_uint4(pkh(a.x, a.y), pkh(a.z, a.w), pkh(b.x, b.y), pkh(b.z, b.w));
}

// ---------------------------------------------------------------------------
// Kernel 2: score GEMM. fp16 MMA, fp32 accum, 3-stage cp.async pipeline,
// N-tile 128 per pass (8 passes) so 2 CTAs fit per SM (regs<=128, smem 70KB).
// ---------------------------------------------------------------------------
__global__ void __launch_bounds__(256, 2)
score_kernel(const float* __restrict__ Ws) {
    extern __shared__ __align__(16) char smem[];
    const uint32_t sb = smem_u32(smem);
    const int tid  = threadIdx.x;
    const int lane = tid & 31;
    const int wid  = tid >> 5;
    const int wy   = wid >> 2;   // 0..1 : M group (64 rows)
    const int wx   = wid & 3;    // 0..3 : N group (32 cols)
    const int b    = blockIdx.y;
    const int v0   = blockIdx.x * 128;

    float* qbs = reinterpret_cast<float*>(smem + SM_QB);
    float* wss = reinterpret_cast<float*>(smem + SM_WS);
#pragma unroll
    for (int i = 0; i < 4; i++) {
        qbs[tid + i * 256] = g_qb[b * HDIM + tid + i * 256];
        wss[tid + i * 256] = Ws[tid + i * 256];
    }

    const __half* keyb = g_key16 + ((size_t)b * VLEN + v0) * HDIM;

    // cp.async mapping: A and B each 128 rows x 64B = 512 x 16B; 2 per thread ea.
    const int grow = tid >> 1;           // 0..127
    const int gseg = (tid & 1) * 2;      // {0,2}

    const uint32_t aoff  = (uint32_t)((lane & 15) * PITCH + (lane >> 4) * 16);
    const uint32_t Abase = sb + (uint32_t)(wy * 64 * PITCH) + aoff;
    const uint32_t Bbase = sb + OFF_B + (uint32_t)(wx * 32 * PITCH) + aoff;

    float d[4][4][4];   // [mt][jj*2+h][quad] : 64 accumulators
#pragma unroll
    for (int mt = 0; mt < 4; mt++)
#pragma unroll
        for (int j = 0; j < 4; j++)
#pragma unroll
            for (int q = 0; q < 4; q++) d[mt][j][q] = 0.0f;
    float part[8];
#pragma unroll
    for (int i = 0; i < 8; i++) part[i] = 0.0f;

    // issue loads of chunk n into stage buffer s
    auto issue_chunk = [&](int n, int s) {
        const int h0 = (n & 31) * 32;
        const int o0 = (n >> 5) * 128;
        const uint32_t bb = sb + (uint32_t)s * BUFSZ;
        cp16(bb + grow * PITCH + gseg * 16,
             keyb + (size_t)grow * HDIM + h0 + gseg * 8);
        cp16(bb + grow * PITCH + (gseg + 1) * 16,
             keyb + (size_t)grow * HDIM + h0 + (gseg + 1) * 8);
        cp16(bb + OFF_B + grow * PITCH + gseg * 16,
             g_wk + (size_t)(o0 + grow) * HDIM + h0 + gseg * 8);
        cp16(bb + OFF_B + grow * PITCH + (gseg + 1) * 16,
             g_wk + (size_t)(o0 + grow) * HDIM + h0 + (gseg + 1) * 8);
        CP_COMMIT();
    };

    // ---- prologue: stages 0..1 in flight ----
    issue_chunk(0, 0);
    issue_chunk(1, 1);

    int stage = 0;
    for (int gc = 0; gc < 256; gc++) {
        if (gc <= 254) { CP_WAIT(1); } else { CP_WAIT(0); }
        __syncthreads();   // chunk gc visible; all warps done with chunk gc-1

        // refill the stage buffer chunk gc-1 vacated
        if (gc < 254) {
            int ns = stage + 2; if (ns >= NSTAGE) ns -= NSTAGE;
            issue_chunk(gc + 2, ns);
        }

        // ---- compute chunk gc ----
        {
            const uint32_t abuf = Abase + (uint32_t)stage * BUFSZ;
            const uint32_t bbuf = Bbase + (uint32_t)stage * BUFSZ;
#pragma unroll
            for (int ks = 0; ks < 2; ks++) {
                uint32_t Bh[2][4];
#pragma unroll
                for (int jj = 0; jj < 2; jj++)
                    ldsm4(Bh[jj], bbuf + jj * (16 * PITCH) + ks * 32);
#pragma unroll
                for (int mt = 0; mt < 4; mt++) {
                    uint32_t Ah[4];
                    ldsm4(Ah, abuf + mt * (16 * PITCH) + ks * 32);
#pragma unroll
                    for (int jj = 0; jj < 2; jj++) {
#pragma unroll
                        for (int h = 0; h < 2; h++)
                            mma_f16(d[mt][jj * 2 + h], Ah, Bh[jj][h], Bh[jj][2 + h]);
                    }
                }
            }
        }

        // ---- end of pass (every 32 chunks): tanh + Ws reduce, reset accums ----
        if ((gc & 31) == 31) {
            const int o0 = (gc >> 5) * 128;
            const int cb = o0 + wx * 32 + (lane & 3) * 2;
#pragma unroll
            for (int mt = 0; mt < 4; mt++) {
#pragma unroll
                for (int j = 0; j < 4; j++) {
                    const int o = cb + j * 8;
                    const float w0 = wss[o], w1 = wss[o + 1];
                    const float q0 = qbs[o], q1 = qbs[o + 1];
                    part[mt * 2 + 0] += w0 * ftanh(d[mt][j][0] + q0) + w1 * ftanh(d[mt][j][1] + q1);
                    part[mt * 2 + 1] += w0 * ftanh(d[mt][j][2] + q0) + w1 * ftanh(d[mt][j][3] + q1);
                    d[mt][j][0] = 0.0f; d[mt][j][1] = 0.0f;
                    d[mt][j][2] = 0.0f; d[mt][j][3] = 0.0f;
                }
            }
        }
        if (++stage == NSTAGE) stage = 0;
    }

    // ---- cross-thread reduction ----
#pragma unroll
    for (int i = 0; i < 8; i++) {
        part[i] += __shfl_xor_sync(0xffffffffu, part[i], 1);
        part[i] += __shfl_xor_sync(0xffffffffu, part[i], 2);
    }
    float* red = reinterpret_cast<float*>(smem + SM_RED);
    if ((lane & 3) == 0) {
        const int r0 = wy * 64 + (lane >> 2);
#pragma unroll
        for (int mt = 0; mt < 4; mt++) {
            red[wx * 128 + r0 + mt * 16]     = part[mt * 2 + 0];
            red[wx * 128 + r0 + mt * 16 + 8] = part[mt * 2 + 1];
        }
    }
    __syncthreads();
    if (tid < 128) {
        const float s = red[tid] + red[128 + tid] + red[256 + tid] + red[384 + tid];
        g_score[b * VLEN + v0 + tid] = s;
    }
}

// ---------------------------------------------------------------------------
// Kernel 3: softmax over V=4096 per batch
// ---------------------------------------------------------------------------
__global__ void softmax_kernel(float* __restrict__ attn_out) {
    __shared__ float red[256];
    const int b = blockIdx.x;
    const int t = threadIdx.x;
    const float* s = g_score + b * VLEN;

    float local[16];
    float mx = -1e30f;
#pragma unroll
    for (int i = 0; i < 16; i++) {
        local[i] = s[t + i * 256];
        mx = fmaxf(mx, local[i]);
    }
    red[t] = mx;
    __syncthreads();
    for (int o = 128; o; o >>= 1) {
        if (t < o) red[t] = fmaxf(red[t], red[t + o]);
        __syncthreads();
    }
    mx = red[0];
    __syncthreads();

    float sum = 0.0f;
#pragma unroll
    for (int i = 0; i < 16; i++) {
        local[i] = expf(local[i] - mx);
        sum += local[i];
    }
    red[t] = sum;
    __syncthreads();
    for (int o = 128; o; o >>= 1) {
        if (t < o) red[t] += red[t + o];
        __syncthreads();
    }
    const float inv = 1.0f / red[0];
#pragma unroll
    for (int i = 0; i < 16; i++) attn_out[b * VLEN + t + i * 256] = local[i] * inv;
}

// ---------------------------------------------------------------------------
// Kernel 4a: context partials with v-split (512 blocks for full-chip MLP)
// ---------------------------------------------------------------------------
__global__ void context_part_kernel(const float* __restrict__ value,
                                    const float* __restrict__ attn) {
    __shared__ float a_s[512];
    const int hc = blockIdx.x, b = blockIdx.y, vs = blockIdx.z;
    const int v0 = vs * 512;
    const float* ap = attn + b * VLEN + v0;
    for (int i = threadIdx.x; i < 512; i += 128) a_s[i] = ap[i];
    __syncthreads();

    const int h = hc * 512 + threadIdx.x * 4;
    const float* vp = value + ((size_t)b * VLEN + v0) * HDIM + h;
    float ax = 0.f, ay = 0.f, az = 0.f, aw = 0.f;
    for (int v = 0; v < 512; v += 8) {
#pragma unroll
        for (int j = 0; j < 8; j++) {
            const float4 x = *reinterpret_cast<const float4*>(vp + (size_t)(v + j) * HDIM);
            const float a = a_s[v + j];
            ax += a * x.x; ay += a * x.y; az += a * x.z; aw += a * x.w;
        }
    }
    *reinterpret_cast<float4*>(g_ctx_part + ((size_t)vs * BATCH + b) * HDIM + h) =
        make_float4(ax, ay, az, aw);
}

// Kernel 4b: reduce 8 partials
__global__ void context_reduce_kernel(float* __restrict__ ctx) {
    const int i = blockIdx.x * 256 + threadIdx.x;
    float s = 0.0f;
#pragma unroll
    for (int vs = 0; vs < 8; vs++) s += g_ctx_part[vs * BATCH * HDIM + i];
    ctx[i] = s;
}

// ---------------------------------------------------------------------------
// Launch. Inputs: query, key, value, Wq, Wk, bias, Ws, bs.
// Output: context (32*1024) then attn (32*4096).
// ---------------------------------------------------------------------------
extern "C" void kernel_launch(void* const* d_in, const int* in_sizes, int n_in,
                              void* d_out, int out_size) {
    const float* query = (const float*)d_in[0];
    const float* key   = (const float*)d_in[1];
    const float* value = (const float*)d_in[2];
    const float* Wq    = (const float*)d_in[3];
    const float* Wk    = (const float*)d_in[4];
    const float* bias  = (const float*)d_in[5];
    const float* Ws    = (const float*)d_in[6];

    float* out  = (float*)d_out;
    float* ctx  = out;                    // (B, 1, H)
    float* attn = out + BATCH * HDIM;     // (B, V)

    cudaFuncSetAttribute(score_kernel, cudaFuncAttributeMaxDynamicSharedMemorySize, SM_TOTAL);

    qb_kernel<<<(BATCH * HDIM * 32) / 256, 256>>>(query, Wq, bias);
    wk_conv_kernel<<<(HDIM * HDIM) / (256 * 4), 256>>>(Wk);
    key_conv_kernel<<<(int)(((size_t)BATCH * VLEN * HDIM) / (256 * 8)), 256>>>(key);
    score_kernel<<<dim3(VLEN / 128, BATCH), 256, SM_TOTAL>>>(Ws);
    softmax_kernel<<<BATCH, 256>>>(attn);
    context_part_kernel<<<dim3(2, BATCH, 8), 128>>>(value, attn);
    context_reduce_kernel<<<(BATCH * HDIM) / 256, 256>>>(ctx);
}

// round 10
// speedup vs baseline: 1.1481x; 1.0486x over previous
#include <cuda_runtime.h>
#include <cuda_fp16.h>
#include <cstdint>

#define BATCH 32
#define VLEN  4096
#define HDIM  1024

// ---------------- device scratch ----------------
__device__ float g_qb[BATCH * HDIM];
__device__ float g_score[BATCH * VLEN];
__device__ __align__(16) __half g_wk[HDIM * HDIM];
__device__ __align__(16) __half g_key16[(size_t)BATCH * VLEN * HDIM];
__device__ float g_ctx_part[8 * BATCH * HDIM];   // v-split context partials

// ---------------- helpers ----------------
__device__ __forceinline__ uint32_t smem_u32(const void* p) {
    uint32_t a;
    asm("{ .reg .u64 t; cvta.to.shared.u64 t, %1; cvt.u32.u64 %0, t; }" : "=r"(a) : "l"(p));
    return a;
}
__device__ __forceinline__ void cp16(uint32_t saddr, const void* g) {
    asm volatile("cp.async.cg.shared.global [%0], [%1], 16;" :: "r"(saddr), "l"(g) : "memory");
}
#define CP_COMMIT()  asm volatile("cp.async.commit_group;" ::: "memory")
#define CP_WAIT(N)   asm volatile("cp.async.wait_group %0;" :: "n"(N) : "memory")

__device__ __forceinline__ void ldsm4(uint32_t* r, uint32_t addr) {
    asm volatile("ldmatrix.sync.aligned.m8n8.x4.shared.b16 {%0,%1,%2,%3}, [%4];"
                 : "=r"(r[0]), "=r"(r[1]), "=r"(r[2]), "=r"(r[3]) : "r"(addr));
}
__device__ __forceinline__ void mma_f16(float* d, const uint32_t* a, uint32_t b0, uint32_t b1) {
    asm volatile("mma.sync.aligned.m16n8k16.row.col.f32.f16.f16.f32 "
                 "{%0,%1,%2,%3}, {%4,%5,%6,%7}, {%8,%9}, {%0,%1,%2,%3};"
                 : "+f"(d[0]), "+f"(d[1]), "+f"(d[2]), "+f"(d[3])
                 : "r"(a[0]), "r"(a[1]), "r"(a[2]), "r"(a[3]), "r"(b0), "r"(b1));
}
__device__ __forceinline__ uint32_t pkh(float a, float b) {
    __half2 h = __floats2half2_rn(a, b);
    return *reinterpret_cast<uint32_t*>(&h);
}
// fast tanh: 1 - 2/(exp(2x)+1); MUFU-based, rel err ~1e-6
__device__ __forceinline__ float ftanh(float x) {
    float e = __expf(2.0f * x);
    return 1.0f - __fdividef(2.0f, e + 1.0f);
}

// ---------------- SMEM layout (bytes) ----------------
// M-tile 64, N-tile 128, K-chunk 32 fp16 (64 B/row), pitch 80 B.
// per stage: [A 64*80 = 5120][B 128*80 = 10240] = 15360; 3 stages.
#define PITCH    80
#define OFF_B    5120
#define BUFSZ    15360
#define NSTAGE   3
#define SM_QB    (NSTAGE * BUFSZ)     // 46080, 1024 floats
#define SM_WS    (SM_QB + 4096)       // 50176
#define SM_RED   (SM_WS + 4096)       // 54272, 256 floats
#define SM_TOTAL (SM_RED + 1024)      // 55296  (x3 CTAs = 166 KB/SM)

// ---------------------------------------------------------------------------
// Kernel 1: qb[b][o] = bias[o] + sum_h Wq[o][h] * query[b][h]
// ---------------------------------------------------------------------------
__global__ void qb_kernel(const float* __restrict__ query,
                          const float* __restrict__ Wq,
                          const float* __restrict__ bias) {
    int w    = (blockIdx.x * blockDim.x + threadIdx.x) >> 5;
    int lane = threadIdx.x & 31;
    int b = w / HDIM;
    int o = w % HDIM;
    const float* wrow = Wq + (size_t)o * HDIM;
    const float* qrow = query + (size_t)b * HDIM;
    float s = 0.0f;
#pragma unroll 8
    for (int h = lane; h < HDIM; h += 32) s += wrow[h] * qrow[h];
#pragma unroll
    for (int off = 16; off; off >>= 1) s += __shfl_xor_sync(0xffffffffu, s, off);
    if (lane == 0) g_qb[w] = s + bias[o];
}

// ---------------------------------------------------------------------------
// Kernel 1b: convert Wk to fp16
// ---------------------------------------------------------------------------
__global__ void wk_conv_kernel(const float* __restrict__ Wk) {
    int i = (blockIdx.x * 256 + threadIdx.x) * 4;
    float4 w = *reinterpret_cast<const float4*>(Wk + i);
    *reinterpret_cast<uint2*>(g_wk + i) = make_uint2(pkh(w.x, w.y), pkh(w.z, w.w));
}

// ---------------------------------------------------------------------------
// Kernel 1c: convert key to fp16 (bandwidth-bound pre-pass)
// ---------------------------------------------------------------------------
__global__ void key_conv_kernel(const float* __restrict__ key) {
    const size_t i = ((size_t)blockIdx.x * 256 + threadIdx.x) * 8;
    const float4 a = *reinterpret_cast<const float4*>(key + i);
    const float4 b = *reinterpret_cast<const float4*>(key + i + 4);
    *reinterpret_cast<uint4*>(g_key16 + i) =
        make_uint4(pkh(a.x, a.y), pkh(a.z, a.w), pkh(b.x, b.y), pkh(b.z, b.w));
}

// ---------------------------------------------------------------------------
// Kernel 2: score GEMM. fp16 MMA, fp32 accum, 3-stage cp.async pipeline.
// CTA = 64 v-rows x 128 o-cols per pass, 8 passes; 3 CTAs/SM target.
// Warps: 2 (M, 32 rows each) x 4 (N, 32 cols each).
// ---------------------------------------------------------------------------
__global__ void __launch_bounds__(256, 3)
score_kernel(const float* __restrict__ Ws) {
    extern __shared__ __align__(16) char smem[];
    const uint32_t sb = smem_u32(smem);
    const int tid  = threadIdx.x;
    const int lane = tid & 31;
    const int wid  = tid >> 5;
    const int wy   = wid >> 2;   // 0..1 : M group (32 rows)
    const int wx   = wid & 3;    // 0..3 : N group (32 cols)
    const int b    = blockIdx.y;
    const int v0   = blockIdx.x * 64;

    float* qbs = reinterpret_cast<float*>(smem + SM_QB);
    float* wss = reinterpret_cast<float*>(smem + SM_WS);
#pragma unroll
    for (int i = 0; i < 4; i++) {
        qbs[tid + i * 256] = g_qb[b * HDIM + tid + i * 256];
        wss[tid + i * 256] = Ws[tid + i * 256];
    }

    const __half* keyb = g_key16 + ((size_t)b * VLEN + v0) * HDIM;

    // cp.async mappings: A 256 x 16B (1/thread), B 512 x 16B (2/thread)
    const int arow = tid >> 2;           // 0..63
    const int aseg = tid & 3;            // 0..3
    const int brow = tid >> 1;           // 0..127
    const int bseg = (tid & 1) * 2;      // {0,2}

    const uint32_t aoff  = (uint32_t)((lane & 15) * PITCH + (lane >> 4) * 16);
    const uint32_t Abase = sb + (uint32_t)(wy * 32 * PITCH) + aoff;
    const uint32_t Bbase = sb + OFF_B + (uint32_t)(wx * 32 * PITCH) + aoff;

    float d[2][4][4];   // [mt][jj*2+h][quad] : 32 accumulators
#pragma unroll
    for (int mt = 0; mt < 2; mt++)
#pragma unroll
        for (int j = 0; j < 4; j++)
#pragma unroll
            for (int q = 0; q < 4; q++) d[mt][j][q] = 0.0f;
    float part[4];
#pragma unroll
    for (int i = 0; i < 4; i++) part[i] = 0.0f;

    // issue loads of chunk n into stage buffer s
    auto issue_chunk = [&](int n, int s) {
        const int h0 = (n & 31) * 32;
        const int o0 = (n >> 5) * 128;
        const uint32_t bb = sb + (uint32_t)s * BUFSZ;
        cp16(bb + arow * PITCH + aseg * 16,
             keyb + (size_t)arow * HDIM + h0 + aseg * 8);
        cp16(bb + OFF_B + brow * PITCH + bseg * 16,
             g_wk + (size_t)(o0 + brow) * HDIM + h0 + bseg * 8);
        cp16(bb + OFF_B + brow * PITCH + (bseg + 1) * 16,
             g_wk + (size_t)(o0 + brow) * HDIM + h0 + (bseg + 1) * 8);
        CP_COMMIT();
    };

    // ---- prologue: stages 0..1 in flight ----
    issue_chunk(0, 0);
    issue_chunk(1, 1);

    int stage = 0;
    for (int gc = 0; gc < 256; gc++) {
        if (gc <= 254) { CP_WAIT(1); } else { CP_WAIT(0); }
        __syncthreads();   // chunk gc visible; all warps done with chunk gc-1

        // refill the stage buffer chunk gc-1 vacated
        if (gc < 254) {
            int ns = stage + 2; if (ns >= NSTAGE) ns -= NSTAGE;
            issue_chunk(gc + 2, ns);
        }

        // ---- compute chunk gc ----
        {
            const uint32_t abuf = Abase + (uint32_t)stage * BUFSZ;
            const uint32_t bbuf = Bbase + (uint32_t)stage * BUFSZ;
#pragma unroll
            for (int ks = 0; ks < 2; ks++) {
                uint32_t Bh[2][4];
#pragma unroll
                for (int jj = 0; jj < 2; jj++)
                    ldsm4(Bh[jj], bbuf + jj * (16 * PITCH) + ks * 32);
                uint32_t Ah[2][4];
#pragma unroll
                for (int mt = 0; mt < 2; mt++)
                    ldsm4(Ah[mt], abuf + mt * (16 * PITCH) + ks * 32);
#pragma unroll
                for (int mt = 0; mt < 2; mt++)
#pragma unroll
                    for (int jj = 0; jj < 2; jj++)
#pragma unroll
                        for (int h = 0; h < 2; h++)
                            mma_f16(d[mt][jj * 2 + h], Ah[mt], Bh[jj][h], Bh[jj][2 + h]);
            }
        }

        // ---- end of pass (every 32 chunks): tanh + Ws reduce, reset accums ----
        if ((gc & 31) == 31) {
            const int o0 = (gc >> 5) * 128;
            const int cb = o0 + wx * 32 + (lane & 3) * 2;
#pragma unroll
            for (int mt = 0; mt < 2; mt++) {
#pragma unroll
                for (int j = 0; j < 4; j++) {
                    const int o = cb + j * 8;
                    const float w0 = wss[o], w1 = wss[o + 1];
                    const float q0 = qbs[o], q1 = qbs[o + 1];
                    part[mt * 2 + 0] += w0 * ftanh(d[mt][j][0] + q0) + w1 * ftanh(d[mt][j][1] + q1);
                    part[mt * 2 + 1] += w0 * ftanh(d[mt][j][2] + q0) + w1 * ftanh(d[mt][j][3] + q1);
                    d[mt][j][0] = 0.0f; d[mt][j][1] = 0.0f;
                    d[mt][j][2] = 0.0f; d[mt][j][3] = 0.0f;
                }
            }
        }
        if (++stage == NSTAGE) stage = 0;
    }

    // ---- cross-thread reduction ----
#pragma unroll
    for (int i = 0; i < 4; i++) {
        part[i] += __shfl_xor_sync(0xffffffffu, part[i], 1);
        part[i] += __shfl_xor_sync(0xffffffffu, part[i], 2);
    }
    float* red = reinterpret_cast<float*>(smem + SM_RED);
    if ((lane & 3) == 0) {
        const int r0 = wy * 32 + (lane >> 2);
#pragma unroll
        for (int mt = 0; mt < 2; mt++) {
            red[wx * 64 + r0 + mt * 16]     = part[mt * 2 + 0];
            red[wx * 64 + r0 + mt * 16 + 8] = part[mt * 2 + 1];
        }
    }
    __syncthreads();
    if (tid < 64) {
        const float s = red[tid] + red[64 + tid] + red[128 + tid] + red[192 + tid];
        g_score[b * VLEN + v0 + tid] = s;
    }
}

// ---------------------------------------------------------------------------
// Kernel 3: softmax over V=4096 per batch
// ---------------------------------------------------------------------------
__global__ void softmax_kernel(float* __restrict__ attn_out) {
    __shared__ float red[256];
    const int b = blockIdx.x;
    const int t = threadIdx.x;
    const float* s = g_score + b * VLEN;

    float local[16];
    float mx = -1e30f;
#pragma unroll
    for (int i = 0; i < 16; i++) {
        local[i] = s[t + i * 256];
        mx = fmaxf(mx, local[i]);
    }
    red[t] = mx;
    __syncthreads();
    for (int o = 128; o; o >>= 1) {
        if (t < o) red[t] = fmaxf(red[t], red[t + o]);
        __syncthreads();
    }
    mx = red[0];
    __syncthreads();

    float sum = 0.0f;
#pragma unroll
    for (int i = 0; i < 16; i++) {
        local[i] = expf(local[i] - mx);
        sum += local[i];
    }
    red[t] = sum;
    __syncthreads();
    for (int o = 128; o; o >>= 1) {
        if (t < o) red[t] += red[t + o];
        __syncthreads();
    }
    const float inv = 1.0f / red[0];
#pragma unroll
    for (int i = 0; i < 16; i++) attn_out[b * VLEN + t + i * 256] = local[i] * inv;
}

// ---------------------------------------------------------------------------
// Kernel 4a: context partials with v-split (512 blocks for full-chip MLP)
// ---------------------------------------------------------------------------
__global__ void context_part_kernel(const float* __restrict__ value,
                                    const float* __restrict__ attn) {
    __shared__ float a_s[512];
    const int hc = blockIdx.x, b = blockIdx.y, vs = blockIdx.z;
    const int v0 = vs * 512;
    const float* ap = attn + b * VLEN + v0;
    for (int i = threadIdx.x; i < 512; i += 128) a_s[i] = ap[i];
    __syncthreads();

    const int h = hc * 512 + threadIdx.x * 4;
    const float* vp = value + ((size_t)b * VLEN + v0) * HDIM + h;
    float ax = 0.f, ay = 0.f, az = 0.f, aw = 0.f;
    for (int v = 0; v < 512; v += 8) {
#pragma unroll
        for (int j = 0; j < 8; j++) {
            const float4 x = *reinterpret_cast<const float4*>(vp + (size_t)(v + j) * HDIM);
            const float a = a_s[v + j];
            ax += a * x.x; ay += a * x.y; az += a * x.z; aw += a * x.w;
        }
    }
    *reinterpret_cast<float4*>(g_ctx_part + ((size_t)vs * BATCH + b) * HDIM + h) =
        make_float4(ax, ay, az, aw);
}

// Kernel 4b: reduce 8 partials
__global__ void context_reduce_kernel(float* __restrict__ ctx) {
    const int i = blockIdx.x * 256 + threadIdx.x;
    float s = 0.0f;
#pragma unroll
    for (int vs = 0; vs < 8; vs++) s += g_ctx_part[vs * BATCH * HDIM + i];
    ctx[i] = s;
}

// ---------------------------------------------------------------------------
// Launch. Inputs: query, key, value, Wq, Wk, bias, Ws, bs.
// Output: context (32*1024) then attn (32*4096).
// ---------------------------------------------------------------------------
extern "C" void kernel_launch(void* const* d_in, const int* in_sizes, int n_in,
                              void* d_out, int out_size) {
    const float* query = (const float*)d_in[0];
    const float* key   = (const float*)d_in[1];
    const float* value = (const float*)d_in[2];
    const float* Wq    = (const float*)d_in[3];
    const float* Wk    = (const float*)d_in[4];
    const float* bias  = (const float*)d_in[5];
    const float* Ws    = (const float*)d_in[6];

    float* out  = (float*)d_out;
    float* ctx  = out;                    // (B, 1, H)
    float* attn = out + BATCH * HDIM;     // (B, V)

    cudaFuncSetAttribute(score_kernel, cudaFuncAttributeMaxDynamicSharedMemorySize, SM_TOTAL);

    qb_kernel<<<(BATCH * HDIM * 32) / 256, 256>>>(query, Wq, bias);
    wk_conv_kernel<<<(HDIM * HDIM) / (256 * 4), 256>>>(Wk);
    key_conv_kernel<<<(int)(((size_t)BATCH * VLEN * HDIM) / (256 * 8)), 256>>>(key);
    score_kernel<<<dim3(VLEN / 64, BATCH), 256, SM_TOTAL>>>(Ws);
    softmax_kernel<<<BATCH, 256>>>(attn);
    context_part_kernel<<<dim3(2, BATCH, 8), 128>>>(value, attn);
    context_reduce_kernel<<<(BATCH * HDIM) / 256, 256>>>(ctx);
}

// round 13
// speedup vs baseline: 1.1823x; 1.0298x over previous
#include <cuda_runtime.h>
#include <cuda_fp16.h>
#include <cstdint>

#define BATCH 32
#define VLEN  4096
#define HDIM  1024

// ---------------- device scratch ----------------
__device__ float g_qb[BATCH * HDIM];
__device__ float g_score[BATCH * VLEN];
__device__ __align__(16) __half g_wk[HDIM * HDIM];
__device__ __align__(16) __half g_key16[(size_t)BATCH * VLEN * HDIM];
__device__ float g_ctx_part[8 * BATCH * HDIM];   // v-split context partials

// ---------------- helpers ----------------
__device__ __forceinline__ uint32_t smem_u32(const void* p) {
    uint32_t a;
    asm("{ .reg .u64 t; cvta.to.shared.u64 t, %1; cvt.u32.u64 %0, t; }" : "=r"(a) : "l"(p));
    return a;
}
__device__ __forceinline__ void cp16(uint32_t saddr, const void* g) {
    asm volatile("cp.async.cg.shared.global [%0], [%1], 16;" :: "r"(saddr), "l"(g) : "memory");
}
#define CP_COMMIT()  asm volatile("cp.async.commit_group;" ::: "memory")
#define CP_WAIT(N)   asm volatile("cp.async.wait_group %0;" :: "n"(N) : "memory")

__device__ __forceinline__ void ldsm4(uint32_t* r, uint32_t addr) {
    asm volatile("ldmatrix.sync.aligned.m8n8.x4.shared.b16 {%0,%1,%2,%3}, [%4];"
                 : "=r"(r[0]), "=r"(r[1]), "=r"(r[2]), "=r"(r[3]) : "r"(addr));
}
__device__ __forceinline__ void mma_f16(float* d, const uint32_t* a, uint32_t b0, uint32_t b1) {
    asm volatile("mma.sync.aligned.m16n8k16.row.col.f32.f16.f16.f32 "
                 "{%0,%1,%2,%3}, {%4,%5,%6,%7}, {%8,%9}, {%0,%1,%2,%3};"
                 : "+f"(d[0]), "+f"(d[1]), "+f"(d[2]), "+f"(d[3])
                 : "r"(a[0]), "r"(a[1]), "r"(a[2]), "r"(a[3]), "r"(b0), "r"(b1));
}
__device__ __forceinline__ uint32_t pkh(float a, float b) {
    __half2 h = __floats2half2_rn(a, b);
    return *reinterpret_cast<uint32_t*>(&h);
}
// fast tanh: 1 - 2/(exp(2x)+1); MUFU-based, rel err ~1e-6
__device__ __forceinline__ float ftanh(float x) {
    float e = __expf(2.0f * x);
    return 1.0f - __fdividef(2.0f, e + 1.0f);
}

// ---------------- SMEM layout (bytes) ----------------
// M-tile 64, N-tile 128, K-chunk 32 fp16 (64 B/row), pitch 80 B.
// per stage: [A 64*80 = 5120][B 128*80 = 10240] = 15360; 3 stages.
#define PITCH    80
#define OFF_B    5120
#define BUFSZ    15360
#define NSTAGE   3
#define SM_QB    (NSTAGE * BUFSZ)     // 46080, 1024 floats
#define SM_WS    (SM_QB + 4096)       // 50176
#define SM_RED   (SM_WS + 4096)       // 54272, 256 floats
#define SM_TOTAL (SM_RED + 1024)      // 55296  (x3 CTAs = 166 KB/SM)

// ---------------------------------------------------------------------------
// Kernel 1 (merged setup): blocks [0,1024) convert Wk to fp16;
// blocks [1024,5120) compute qb[b][o] = bias[o] + sum_h Wq[o][h]*query[b][h]
// (one warp per (b,o): 32768 warps = 4096 blocks x 8 warps).
// ---------------------------------------------------------------------------
__global__ void setup_kernel(const float* __restrict__ query,
                             const float* __restrict__ Wq,
                             const float* __restrict__ bias,
                             const float* __restrict__ Wk) {
    if (blockIdx.x < 1024) {
        int i = (blockIdx.x * 256 + threadIdx.x) * 4;
        float4 w = *reinterpret_cast<const float4*>(Wk + i);
        *reinterpret_cast<uint2*>(g_wk + i) = make_uint2(pkh(w.x, w.y), pkh(w.z, w.w));
    } else {
        int w    = (((int)blockIdx.x - 1024) * 256 + (int)threadIdx.x) >> 5;
        int lane = threadIdx.x & 31;
        int b = w / HDIM;
        int o = w % HDIM;
        const float* wrow = Wq + (size_t)o * HDIM;
        const float* qrow = query + (size_t)b * HDIM;
        float s = 0.0f;
#pragma unroll 8
        for (int h = lane; h < HDIM; h += 32) s += wrow[h] * qrow[h];
#pragma unroll
        for (int off = 16; off; off >>= 1) s += __shfl_xor_sync(0xffffffffu, s, off);
        if (lane == 0) g_qb[w] = s + bias[o];
    }
}

// ---------------------------------------------------------------------------
// Kernel 2: score GEMM. fp16 MMA, fp32 accum. CTA = 64 v-rows x 128 o-cols
// per pass, 8 passes; 3 CTAs/SM. Prologue converts this CTA's own 64x1024
// key block fp32->fp16 (stcg). A-tile in the mainloop uses plain
// LDG->reg->STS (pipelined one iteration ahead; coherent with same-kernel
// stores). B-tile stays cp.async from g_wk (written by the prior kernel).
// ---------------------------------------------------------------------------
__global__ void __launch_bounds__(256, 3)
score_kernel(const float* __restrict__ key, const float* __restrict__ Ws) {
    extern __shared__ __align__(16) char smem[];
    const uint32_t sb = smem_u32(smem);
    const int tid  = threadIdx.x;
    const int lane = tid & 31;
    const int wid  = tid >> 5;
    const int wy   = wid >> 2;   // 0..1 : M group (32 rows)
    const int wx   = wid & 3;    // 0..3 : N group (32 cols)
    const int b    = blockIdx.y;
    const int v0   = blockIdx.x * 64;

    const size_t kbase = ((size_t)b * VLEN + v0) * HDIM;

    // ---- prologue: convert this CTA's 64x1024 key block to fp16 ----
    {
        const float* kf = key + kbase;
        __half* kh = g_key16 + kbase;
#pragma unroll 4
        for (int it = 0; it < 32; it++) {
            const int e = (tid + it * 256) * 8;
            const float4 a = *reinterpret_cast<const float4*>(kf + e);
            const float4 c = *reinterpret_cast<const float4*>(kf + e + 4);
            __stcg(reinterpret_cast<uint4*>(kh + e),
                   make_uint4(pkh(a.x, a.y), pkh(a.z, a.w), pkh(c.x, c.y), pkh(c.z, c.w)));
        }
        __threadfence();
    }

    float* qbs = reinterpret_cast<float*>(smem + SM_QB);
    float* wss = reinterpret_cast<float*>(smem + SM_WS);
#pragma unroll
    for (int i = 0; i < 4; i++) {
        qbs[tid + i * 256] = g_qb[b * HDIM + tid + i * 256];
        wss[tid + i * 256] = Ws[tid + i * 256];
    }
    __syncthreads();   // conversion + staging visible to all warps

    const __half* keyb = g_key16 + kbase;

    // mappings: A 256 x 16B (1/thread, plain LDG); B 512 x 16B (2/thread, cp.async)
    const int arow = tid >> 2;           // 0..63
    const int aseg = tid & 3;            // 0..3
    const int brow = tid >> 1;           // 0..127
    const int bseg = (tid & 1) * 2;      // {0,2}

    const uint32_t aoff  = (uint32_t)((lane & 15) * PITCH + (lane >> 4) * 16);
    const uint32_t Abase = sb + (uint32_t)(wy * 32 * PITCH) + aoff;
    const uint32_t Bbase = sb + OFF_B + (uint32_t)(wx * 32 * PITCH) + aoff;

    const uint32_t sa_a  = (uint32_t)(arow * PITCH + aseg * 16);
    const uint32_t sa_b0 = (uint32_t)(OFF_B + brow * PITCH + bseg * 16);
    const __half* kap = keyb + (size_t)arow * HDIM + aseg * 8;
    const __half* wbp = g_wk + (size_t)brow * HDIM + bseg * 8;

    float d[2][4][4];   // 32 accumulators
#pragma unroll
    for (int mt = 0; mt < 2; mt++)
#pragma unroll
        for (int j = 0; j < 4; j++)
#pragma unroll
            for (int q = 0; q < 4; q++) d[mt][j][q] = 0.0f;
    float part[4];
#pragma unroll
    for (int i = 0; i < 4; i++) part[i] = 0.0f;

    // B: issue cp.async of chunk n into stage s (one commit group per chunk)
    auto issue_b = [&](int n, int s) {
        const int oh = (n >> 5) * (128 * HDIM) + (n & 31) * 32;
        const uint32_t bb = sb + (uint32_t)s * BUFSZ;
        cp16(bb + sa_b0, wbp + oh);
        cp16(bb + sa_b0 + 16, wbp + oh + 8);
        CP_COMMIT();
    };
    // A: global address of this thread's 16B segment for chunk n
    auto a_addr = [&](int n) { return kap + (n & 31) * 32; };

    // ---- pipeline prologue ----
    uint4 a0    = *reinterpret_cast<const uint4*>(a_addr(0));
    uint4 apend = *reinterpret_cast<const uint4*>(a_addr(1));  // A of chunk 1
    issue_b(0, 0);
    issue_b(1, 1);
    *reinterpret_cast<uint4*>(smem + sa_a) = a0;               // A chunk 0 -> stage 0

    int stage = 0;
    for (int gc = 0; gc < 256; gc++) {
        if (gc <= 254) { CP_WAIT(1); } else { CP_WAIT(0); }
        __syncthreads();   // chunk gc (A sts'd earlier, B landed) visible; gc-1 done

        // STS pending A (chunk gc+1) into its stage buffer
        if (gc <= 254) {
            int s1 = stage + 1; if (s1 == NSTAGE) s1 = 0;
            *reinterpret_cast<uint4*>(smem + (size_t)s1 * BUFSZ + sa_a) = apend;
        }
        // fetch A of chunk gc+2; issue B of chunk gc+2
        if (gc <= 253) {
            apend = *reinterpret_cast<const uint4*>(a_addr(gc + 2));
            int ns = stage + 2; if (ns >= NSTAGE) ns -= NSTAGE;
            issue_b(gc + 2, ns);
        }

        // ---- compute chunk gc ----
        {
            const uint32_t abuf = Abase + (uint32_t)stage * BUFSZ;
            const uint32_t bbuf = Bbase + (uint32_t)stage * BUFSZ;
#pragma unroll
            for (int ks = 0; ks < 2; ks++) {
                uint32_t Bh[2][4];
#pragma unroll
                for (int jj = 0; jj < 2; jj++)
                    ldsm4(Bh[jj], bbuf + jj * (16 * PITCH) + ks * 32);
                uint32_t Ah[2][4];
#pragma unroll
                for (int mt = 0; mt < 2; mt++)
                    ldsm4(Ah[mt], abuf + mt * (16 * PITCH) + ks * 32);
#pragma unroll
                for (int mt = 0; mt < 2; mt++)
#pragma unroll
                    for (int jj = 0; jj < 2; jj++)
#pragma unroll
                        for (int h = 0; h < 2; h++)
                            mma_f16(d[mt][jj * 2 + h], Ah[mt], Bh[jj][h], Bh[jj][2 + h]);
            }
        }

        // ---- end of pass (every 32 chunks): tanh + Ws reduce, reset accums ----
        if ((gc & 31) == 31) {
            const int o0 = (gc >> 5) * 128;
            const int cb = o0 + wx * 32 + (lane & 3) * 2;
#pragma unroll
            for (int mt = 0; mt < 2; mt++) {
#pragma unroll
                for (int j = 0; j < 4; j++) {
                    const int o = cb + j * 8;
                    const float w0 = wss[o], w1 = wss[o + 1];
                    const float q0 = qbs[o], q1 = qbs[o + 1];
                    part[mt * 2 + 0] += w0 * ftanh(d[mt][j][0] + q0) + w1 * ftanh(d[mt][j][1] + q1);
                    part[mt * 2 + 1] += w0 * ftanh(d[mt][j][2] + q0) + w1 * ftanh(d[mt][j][3] + q1);
                    d[mt][j][0] = 0.0f; d[mt][j][1] = 0.0f;
                    d[mt][j][2] = 0.0f; d[mt][j][3] = 0.0f;
                }
            }
        }
        if (++stage == NSTAGE) stage = 0;
    }

    // ---- cross-thread reduction ----
#pragma unroll
    for (int i = 0; i < 4; i++) {
        part[i] += __shfl_xor_sync(0xffffffffu, part[i], 1);
        part[i] += __shfl_xor_sync(0xffffffffu, part[i], 2);
    }
    float* red = reinterpret_cast<float*>(smem + SM_RED);
    if ((lane & 3) == 0) {
        const int r0 = wy * 32 + (lane >> 2);
#pragma unroll
        for (int mt = 0; mt < 2; mt++) {
            red[wx * 64 + r0 + mt * 16]     = part[mt * 2 + 0];
            red[wx * 64 + r0 + mt * 16 + 8] = part[mt * 2 + 1];
        }
    }
    __syncthreads();
    if (tid < 64) {
        const float s = red[tid] + red[64 + tid] + red[128 + tid] + red[192 + tid];
        g_score[b * VLEN + v0 + tid] = s;
    }
}

// ---------------------------------------------------------------------------
// Kernel 3: softmax over V=4096 per batch
// ---------------------------------------------------------------------------
__global__ void softmax_kernel(float* __restrict__ attn_out) {
    __shared__ float red[256];
    const int b = blockIdx.x;
    const int t = threadIdx.x;
    const float* s = g_score + b * VLEN;

    float local[16];
    float mx = -1e30f;
#pragma unroll
    for (int i = 0; i < 16; i++) {
        local[i] = s[t + i * 256];
        mx = fmaxf(mx, local[i]);
    }
    red[t] = mx;
    __syncthreads();
    for (int o = 128; o; o >>= 1) {
        if (t < o) red[t] = fmaxf(red[t], red[t + o]);
        __syncthreads();
    }
    mx = red[0];
    __syncthreads();

    float sum = 0.0f;
#pragma unroll
    for (int i = 0; i < 16; i++) {
        local[i] = expf(local[i] - mx);
        sum += local[i];
    }
    red[t] = sum;
    __syncthreads();
    for (int o = 128; o; o >>= 1) {
        if (t < o) red[t] += red[t + o];
        __syncthreads();
    }
    const float inv = 1.0f / red[0];
#pragma unroll
    for (int i = 0; i < 16; i++) attn_out[b * VLEN + t + i * 256] = local[i] * inv;
}

// ---------------------------------------------------------------------------
// Kernel 4a: context partials with v-split (512 blocks for full-chip MLP)
// ---------------------------------------------------------------------------
__global__ void context_part_kernel(const float* __restrict__ value,
                                    const float* __restrict__ attn) {
    __shared__ float a_s[512];
    const int hc = blockIdx.x, b = blockIdx.y, vs = blockIdx.z;
    const int v0 = vs * 512;
    const float* ap = attn + b * VLEN + v0;
    for (int i = threadIdx.x; i < 512; i += 128) a_s[i] = ap[i];
    __syncthreads();

    const int h = hc * 512 + threadIdx.x * 4;
    const float* vp = value + ((size_t)b * VLEN + v0) * HDIM + h;
    float ax = 0.f, ay = 0.f, az = 0.f, aw = 0.f;
    for (int v = 0; v < 512; v += 8) {
#pragma unroll
        for (int j = 0; j < 8; j++) {
            const float4 x = *reinterpret_cast<const float4*>(vp + (size_t)(v + j) * HDIM);
            const float a = a_s[v + j];
            ax += a * x.x; ay += a * x.y; az += a * x.z; aw += a * x.w;
        }
    }
    *reinterpret_cast<float4*>(g_ctx_part + ((size_t)vs * BATCH + b) * HDIM + h) =
        make_float4(ax, ay, az, aw);
}

// Kernel 4b: reduce 8 partials
__global__ void context_reduce_kernel(float* __restrict__ ctx) {
    const int i = blockIdx.x * 256 + threadIdx.x;
    float s = 0.0f;
#pragma unroll
    for (int vs = 0; vs < 8; vs++) s += g_ctx_part[vs * BATCH * HDIM + i];
    ctx[i] = s;
}

// ---------------------------------------------------------------------------
// Launch. Inputs: query, key, value, Wq, Wk, bias, Ws, bs.
// Output: context (32*1024) then attn (32*4096).
// ---------------------------------------------------------------------------
extern "C" void kernel_launch(void* const* d_in, const int* in_sizes, int n_in,
                              void* d_out, int out_size) {
    const float* query = (const float*)d_in[0];
    const float* key   = (const float*)d_in[1];
    const float* value = (const float*)d_in[2];
    const float* Wq    = (const float*)d_in[3];
    const float* Wk    = (const float*)d_in[4];
    const float* bias  = (const float*)d_in[5];
    const float* Ws    = (const float*)d_in[6];

    float* out  = (float*)d_out;
    float* ctx  = out;                    // (B, 1, H)
    float* attn = out + BATCH * HDIM;     // (B, V)

    cudaFuncSetAttribute(score_kernel, cudaFuncAttributeMaxDynamicSharedMemorySize, SM_TOTAL);

    setup_kernel<<<5120, 256>>>(query, Wq, bias, Wk);   // 1024 Wk-conv + 4096 qb
    score_kernel<<<dim3(VLEN / 64, BATCH), 256, SM_TOTAL>>>(key, Ws);
    softmax_kernel<<<BATCH, 256>>>(attn);
    context_part_kernel<<<dim3(2, BATCH, 8), 128>>>(value, attn);
    context_reduce_kernel<<<(BATCH * HDIM) / 256, 256>>>(ctx);
}

// round 14
// speedup vs baseline: 1.1920x; 1.0082x over previous
#include <cuda_runtime.h>
#include <cuda_fp16.h>
#include <cstdint>

#define BATCH 32
#define VLEN  4096
#define HDIM  1024

// ---------------- device scratch ----------------
__device__ float g_qb[BATCH * HDIM];
__device__ float g_score[BATCH * VLEN];
__device__ __align__(16) __half g_wk[HDIM * HDIM];
__device__ __align__(16) __half g_key16[(size_t)BATCH * VLEN * HDIM];
__device__ float g_ctx_part[16 * BATCH * HDIM];   // v-split context partials

// ---------------- helpers ----------------
__device__ __forceinline__ uint32_t smem_u32(const void* p) {
    uint32_t a;
    asm("{ .reg .u64 t; cvta.to.shared.u64 t, %1; cvt.u32.u64 %0, t; }" : "=r"(a) : "l"(p));
    return a;
}
__device__ __forceinline__ void cp16(uint32_t saddr, const void* g) {
    asm volatile("cp.async.cg.shared.global [%0], [%1], 16;" :: "r"(saddr), "l"(g) : "memory");
}
#define CP_COMMIT()  asm volatile("cp.async.commit_group;" ::: "memory")
#define CP_WAIT(N)   asm volatile("cp.async.wait_group %0;" :: "n"(N) : "memory")

__device__ __forceinline__ void ldsm4(uint32_t* r, uint32_t addr) {
    asm volatile("ldmatrix.sync.aligned.m8n8.x4.shared.b16 {%0,%1,%2,%3}, [%4];"
                 : "=r"(r[0]), "=r"(r[1]), "=r"(r[2]), "=r"(r[3]) : "r"(addr));
}
__device__ __forceinline__ void mma_f16(float* d, const uint32_t* a, uint32_t b0, uint32_t b1) {
    asm volatile("mma.sync.aligned.m16n8k16.row.col.f32.f16.f16.f32 "
                 "{%0,%1,%2,%3}, {%4,%5,%6,%7}, {%8,%9}, {%0,%1,%2,%3};"
                 : "+f"(d[0]), "+f"(d[1]), "+f"(d[2]), "+f"(d[3])
                 : "r"(a[0]), "r"(a[1]), "r"(a[2]), "r"(a[3]), "r"(b0), "r"(b1));
}
__device__ __forceinline__ uint32_t pkh(float a, float b) {
    __half2 h = __floats2half2_rn(a, b);
    return *reinterpret_cast<uint32_t*>(&h);
}
// fast tanh: 1 - 2/(exp(2x)+1); MUFU-based, rel err ~1e-6
__device__ __forceinline__ float ftanh(float x) {
    float e = __expf(2.0f * x);
    return 1.0f - __fdividef(2.0f, e + 1.0f);
}

// ---------------- SMEM layout (bytes) ----------------
// M-tile 64, N-tile 128, K-chunk 32 fp16 (64 B/row), pitch 80 B.
// per stage: [A 64*80 = 5120][B 128*80 = 10240] = 15360; 3 stages.
#define PITCH    80
#define OFF_B    5120
#define BUFSZ    15360
#define NSTAGE   3
#define SM_QB    (NSTAGE * BUFSZ)     // 46080, 1024 floats
#define SM_WS    (SM_QB + 4096)       // 50176
#define SM_RED   (SM_WS + 4096)       // 54272, 256 floats
#define SM_TOTAL (SM_RED + 1024)      // 55296  (x3 CTAs = 166 KB/SM)

// ---------------------------------------------------------------------------
// Kernel 1 (merged setup): blocks [0,1024) convert Wk to fp16;
// blocks [1024,5120) compute qb[b][o] = bias[o] + sum_h Wq[o][h]*query[b][h]
// ---------------------------------------------------------------------------
__global__ void setup_kernel(const float* __restrict__ query,
                             const float* __restrict__ Wq,
                             const float* __restrict__ bias,
                             const float* __restrict__ Wk) {
    if (blockIdx.x < 1024) {
        int i = (blockIdx.x * 256 + threadIdx.x) * 4;
        float4 w = *reinterpret_cast<const float4*>(Wk + i);
        *reinterpret_cast<uint2*>(g_wk + i) = make_uint2(pkh(w.x, w.y), pkh(w.z, w.w));
    } else {
        int w    = (((int)blockIdx.x - 1024) * 256 + (int)threadIdx.x) >> 5;
        int lane = threadIdx.x & 31;
        int b = w / HDIM;
        int o = w % HDIM;
        const float* wrow = Wq + (size_t)o * HDIM;
        const float* qrow = query + (size_t)b * HDIM;
        float s = 0.0f;
#pragma unroll 8
        for (int h = lane; h < HDIM; h += 32) s += wrow[h] * qrow[h];
#pragma unroll
        for (int off = 16; off; off >>= 1) s += __shfl_xor_sync(0xffffffffu, s, off);
        if (lane == 0) g_qb[w] = s + bias[o];
    }
}

// ---------------------------------------------------------------------------
// Kernel 2: score GEMM. fp16 MMA, fp32 accum. CTA = 64 v-rows x 128 o-cols
// per pass, 8 passes; 3 CTAs/SM. Prologue converts this CTA's own 64x1024
// key block fp32->fp16 (stcg). A-tile: plain LDG->reg->STS pipeline;
// B-tile: cp.async from g_wk.
// ---------------------------------------------------------------------------
__global__ void __launch_bounds__(256, 3)
score_kernel(const float* __restrict__ key, const float* __restrict__ Ws) {
    extern __shared__ __align__(16) char smem[];
    const uint32_t sb = smem_u32(smem);
    const int tid  = threadIdx.x;
    const int lane = tid & 31;
    const int wid  = tid >> 5;
    const int wy   = wid >> 2;   // 0..1 : M group (32 rows)
    const int wx   = wid & 3;    // 0..3 : N group (32 cols)
    const int b    = blockIdx.y;
    const int v0   = blockIdx.x * 64;

    const size_t kbase = ((size_t)b * VLEN + v0) * HDIM;

    // ---- prologue: convert this CTA's 64x1024 key block to fp16 ----
    {
        const float* kf = key + kbase;
        __half* kh = g_key16 + kbase;
#pragma unroll 4
        for (int it = 0; it < 32; it++) {
            const int e = (tid + it * 256) * 8;
            const float4 a = *reinterpret_cast<const float4*>(kf + e);
            const float4 c = *reinterpret_cast<const float4*>(kf + e + 4);
            __stcg(reinterpret_cast<uint4*>(kh + e),
                   make_uint4(pkh(a.x, a.y), pkh(a.z, a.w), pkh(c.x, c.y), pkh(c.z, c.w)));
        }
        __threadfence();
    }

    float* qbs = reinterpret_cast<float*>(smem + SM_QB);
    float* wss = reinterpret_cast<float*>(smem + SM_WS);
#pragma unroll
    for (int i = 0; i < 4; i++) {
        qbs[tid + i * 256] = g_qb[b * HDIM + tid + i * 256];
        wss[tid + i * 256] = Ws[tid + i * 256];
    }
    __syncthreads();   // conversion + staging visible to all warps

    const __half* keyb = g_key16 + kbase;

    // mappings: A 256 x 16B (1/thread, plain LDG); B 512 x 16B (2/thread, cp.async)
    const int arow = tid >> 2;           // 0..63
    const int aseg = tid & 3;            // 0..3
    const int brow = tid >> 1;           // 0..127
    const int bseg = (tid & 1) * 2;      // {0,2}

    const uint32_t aoff  = (uint32_t)((lane & 15) * PITCH + (lane >> 4) * 16);
    const uint32_t Abase = sb + (uint32_t)(wy * 32 * PITCH) + aoff;
    const uint32_t Bbase = sb + OFF_B + (uint32_t)(wx * 32 * PITCH) + aoff;

    const uint32_t sa_a  = (uint32_t)(arow * PITCH + aseg * 16);
    const uint32_t sa_b0 = (uint32_t)(OFF_B + brow * PITCH + bseg * 16);
    const __half* kap = keyb + (size_t)arow * HDIM + aseg * 8;
    const __half* wbp = g_wk + (size_t)brow * HDIM + bseg * 8;

    float d[2][4][4];   // 32 accumulators
#pragma unroll
    for (int mt = 0; mt < 2; mt++)
#pragma unroll
        for (int j = 0; j < 4; j++)
#pragma unroll
            for (int q = 0; q < 4; q++) d[mt][j][q] = 0.0f;
    float part[4];
#pragma unroll
    for (int i = 0; i < 4; i++) part[i] = 0.0f;

    auto issue_b = [&](int n, int s) {
        const int oh = (n >> 5) * (128 * HDIM) + (n & 31) * 32;
        const uint32_t bb = sb + (uint32_t)s * BUFSZ;
        cp16(bb + sa_b0, wbp + oh);
        cp16(bb + sa_b0 + 16, wbp + oh + 8);
        CP_COMMIT();
    };
    auto a_addr = [&](int n) { return kap + (n & 31) * 32; };

    // ---- pipeline prologue ----
    uint4 a0    = *reinterpret_cast<const uint4*>(a_addr(0));
    uint4 apend = *reinterpret_cast<const uint4*>(a_addr(1));
    issue_b(0, 0);
    issue_b(1, 1);
    *reinterpret_cast<uint4*>(smem + sa_a) = a0;

    int stage = 0;
    for (int gc = 0; gc < 256; gc++) {
        if (gc <= 254) { CP_WAIT(1); } else { CP_WAIT(0); }
        __syncthreads();

        if (gc <= 254) {
            int s1 = stage + 1; if (s1 == NSTAGE) s1 = 0;
            *reinterpret_cast<uint4*>(smem + (size_t)s1 * BUFSZ + sa_a) = apend;
        }
        if (gc <= 253) {
            apend = *reinterpret_cast<const uint4*>(a_addr(gc + 2));
            int ns = stage + 2; if (ns >= NSTAGE) ns -= NSTAGE;
            issue_b(gc + 2, ns);
        }

        // ---- compute chunk gc ----
        {
            const uint32_t abuf = Abase + (uint32_t)stage * BUFSZ;
            const uint32_t bbuf = Bbase + (uint32_t)stage * BUFSZ;
#pragma unroll
            for (int ks = 0; ks < 2; ks++) {
                uint32_t Bh[2][4];
#pragma unroll
                for (int jj = 0; jj < 2; jj++)
                    ldsm4(Bh[jj], bbuf + jj * (16 * PITCH) + ks * 32);
                uint32_t Ah[2][4];
#pragma unroll
                for (int mt = 0; mt < 2; mt++)
                    ldsm4(Ah[mt], abuf + mt * (16 * PITCH) + ks * 32);
#pragma unroll
                for (int mt = 0; mt < 2; mt++)
#pragma unroll
                    for (int jj = 0; jj < 2; jj++)
#pragma unroll
                        for (int h = 0; h < 2; h++)
                            mma_f16(d[mt][jj * 2 + h], Ah[mt], Bh[jj][h], Bh[jj][2 + h]);
            }
        }

        // ---- end of pass (every 32 chunks): tanh + Ws reduce, reset accums ----
        if ((gc & 31) == 31) {
            const int o0 = (gc >> 5) * 128;
            const int cb = o0 + wx * 32 + (lane & 3) * 2;
#pragma unroll
            for (int mt = 0; mt < 2; mt++) {
#pragma unroll
                for (int j = 0; j < 4; j++) {
                    const int o = cb + j * 8;
                    const float w0 = wss[o], w1 = wss[o + 1];
                    const float q0 = qbs[o], q1 = qbs[o + 1];
                    part[mt * 2 + 0] += w0 * ftanh(d[mt][j][0] + q0) + w1 * ftanh(d[mt][j][1] + q1);
                    part[mt * 2 + 1] += w0 * ftanh(d[mt][j][2] + q0) + w1 * ftanh(d[mt][j][3] + q1);
                    d[mt][j][0] = 0.0f; d[mt][j][1] = 0.0f;
                    d[mt][j][2] = 0.0f; d[mt][j][3] = 0.0f;
                }
            }
        }
        if (++stage == NSTAGE) stage = 0;
    }

    // ---- cross-thread reduction ----
#pragma unroll
    for (int i = 0; i < 4; i++) {
        part[i] += __shfl_xor_sync(0xffffffffu, part[i], 1);
        part[i] += __shfl_xor_sync(0xffffffffu, part[i], 2);
    }
    float* red = reinterpret_cast<float*>(smem + SM_RED);
    if ((lane & 3) == 0) {
        const int r0 = wy * 32 + (lane >> 2);
#pragma unroll
        for (int mt = 0; mt < 2; mt++) {
            red[wx * 64 + r0 + mt * 16]     = part[mt * 2 + 0];
            red[wx * 64 + r0 + mt * 16 + 8] = part[mt * 2 + 1];
        }
    }
    __syncthreads();
    if (tid < 64) {
        const float s = red[tid] + red[64 + tid] + red[128 + tid] + red[192 + tid];
        g_score[b * VLEN + v0 + tid] = s;
    }
}

// ---------------------------------------------------------------------------
// Kernel 3: softmax over V=4096 per batch
// ---------------------------------------------------------------------------
__global__ void softmax_kernel(float* __restrict__ attn_out) {
    __shared__ float red[256];
    const int b = blockIdx.x;
    const int t = threadIdx.x;
    const float* s = g_score + b * VLEN;

    float local[16];
    float mx = -1e30f;
#pragma unroll
    for (int i = 0; i < 16; i++) {
        local[i] = s[t + i * 256];
        mx = fmaxf(mx, local[i]);
    }
    red[t] = mx;
    __syncthreads();
    for (int o = 128; o; o >>= 1) {
        if (t < o) red[t] = fmaxf(red[t], red[t + o]);
        __syncthreads();
    }
    mx = red[0];
    __syncthreads();

    float sum = 0.0f;
#pragma unroll
    for (int i = 0; i < 16; i++) {
        local[i] = expf(local[i] - mx);
        sum += local[i];
    }
    red[t] = sum;
    __syncthreads();
    for (int o = 128; o; o >>= 1) {
        if (t < o) red[t] += red[t + o];
        __syncthreads();
    }
    const float inv = 1.0f / red[0];
#pragma unroll
    for (int i = 0; i < 16; i++) attn_out[b * VLEN + t + i * 256] = local[i] * inv;
}

// ---------------------------------------------------------------------------
// Kernel 4a: context partials. grid (b=32, vs=16) x 256 threads; each block
// covers all 1024 h (256 threads x float4) over 256 v-rows. 2x threads and
// MLP vs previous version to push DRAM toward saturation.
// ---------------------------------------------------------------------------
__global__ void __launch_bounds__(256, 4)
context_part_kernel(const float* __restrict__ value,
                    const float* __restrict__ attn) {
    __shared__ float a_s[256];
    const int b = blockIdx.x, vs = blockIdx.y;
    const int v0 = vs * 256;
    const float* ap = attn + b * VLEN + v0;
    if (threadIdx.x < 256) a_s[threadIdx.x] = ap[threadIdx.x];
    __syncthreads();

    const int h = threadIdx.x * 4;
    const float* vp = value + ((size_t)b * VLEN + v0) * HDIM + h;
    float ax = 0.f, ay = 0.f, az = 0.f, aw = 0.f;
    for (int v = 0; v < 256; v += 8) {
#pragma unroll
        for (int j = 0; j < 8; j++) {
            const float4 x = *reinterpret_cast<const float4*>(vp + (size_t)(v + j) * HDIM);
            const float a = a_s[v + j];
            ax += a * x.x; ay += a * x.y; az += a * x.z; aw += a * x.w;
        }
    }
    *reinterpret_cast<float4*>(g_ctx_part + ((size_t)vs * BATCH + b) * HDIM + h) =
        make_float4(ax, ay, az, aw);
}

// Kernel 4b: reduce 16 partials
__global__ void context_reduce_kernel(float* __restrict__ ctx) {
    const int i = blockIdx.x * 256 + threadIdx.x;
    float s = 0.0f;
#pragma unroll
    for (int vs = 0; vs < 16; vs++) s += g_ctx_part[vs * BATCH * HDIM + i];
    ctx[i] = s;
}

// ---------------------------------------------------------------------------
// Launch. Inputs: query, key, value, Wq, Wk, bias, Ws, bs.
// Output: context (32*1024) then attn (32*4096).
// ---------------------------------------------------------------------------
extern "C" void kernel_launch(void* const* d_in, const int* in_sizes, int n_in,
                              void* d_out, int out_size) {
    const float* query = (const float*)d_in[0];
    const float* key   = (const float*)d_in[1];
    const float* value = (const float*)d_in[2];
    const float* Wq    = (const float*)d_in[3];
    const float* Wk    = (const float*)d_in[4];
    const float* bias  = (const float*)d_in[5];
    const float* Ws    = (const float*)d_in[6];

    float* out  = (float*)d_out;
    float* ctx  = out;                    // (B, 1, H)
    float* attn = out + BATCH * HDIM;     // (B, V)

    cudaFuncSetAttribute(score_kernel, cudaFuncAttributeMaxDynamicSharedMemorySize, SM_TOTAL);

    setup_kernel<<<5120, 256>>>(query, Wq, bias, Wk);   // 1024 Wk-conv + 4096 qb
    score_kernel<<<dim3(VLEN / 64, BATCH), 256, SM_TOTAL>>>(key, Ws);
    softmax_kernel<<<BATCH, 256>>>(attn);
    context_part_kernel<<<dim3(BATCH, 16), 256>>>(value, attn);
    context_reduce_kernel<<<(BATCH * HDIM) / 256, 256>>>(ctx);
}

// round 15
// speedup vs baseline: 1.2002x; 1.0069x over previous
#include <cuda_runtime.h>
#include <cuda_fp16.h>
#include <cstdint>

#define BATCH 32
#define VLEN  4096
#define HDIM  1024

// ---------------- device scratch ----------------
__device__ float g_qb[BATCH * HDIM];
__device__ float g_score[BATCH * VLEN];
__device__ __align__(16) __half g_wk[HDIM * HDIM];
__device__ __align__(16) __half g_key16[(size_t)BATCH * VLEN * HDIM];
__device__ float g_ctx_part[16 * BATCH * HDIM];

// persistent-kernel scheduling state (zeroed by setup_kernel each launch)
__device__ int g_next;
__device__ int g_done_score[BATCH];   // 64 tiles per b
__device__ int g_soft_flag[BATCH];
__device__ int g_ctx_done[BATCH];     // 16 partial jobs per b

#define N_SCORE   2048
#define J_SOFT    (N_SCORE)            // 2048..2079
#define J_CTX     (J_SOFT + BATCH)     // 2080..2591
#define J_RED     (J_CTX + BATCH * 16) // 2592..2623
#define N_JOBS    (J_RED + BATCH)      // 2624
#define GRID_P    444                  // 148 SMs x 3 CTAs

// ---------------- helpers ----------------
__device__ __forceinline__ uint32_t smem_u32(const void* p) {
    uint32_t a;
    asm("{ .reg .u64 t; cvta.to.shared.u64 t, %1; cvt.u32.u64 %0, t; }" : "=r"(a) : "l"(p));
    return a;
}
__device__ __forceinline__ void cp16(uint32_t saddr, const void* g) {
    asm volatile("cp.async.cg.shared.global [%0], [%1], 16;" :: "r"(saddr), "l"(g) : "memory");
}
#define CP_COMMIT()  asm volatile("cp.async.commit_group;" ::: "memory")
#define CP_WAIT(N)   asm volatile("cp.async.wait_group %0;" :: "n"(N) : "memory")

__device__ __forceinline__ void ldsm4(uint32_t* r, uint32_t addr) {
    asm volatile("ldmatrix.sync.aligned.m8n8.x4.shared.b16 {%0,%1,%2,%3}, [%4];"
                 : "=r"(r[0]), "=r"(r[1]), "=r"(r[2]), "=r"(r[3]) : "r"(addr));
}
__device__ __forceinline__ void mma_f16(float* d, const uint32_t* a, uint32_t b0, uint32_t b1) {
    asm volatile("mma.sync.aligned.m16n8k16.row.col.f32.f16.f16.f32 "
                 "{%0,%1,%2,%3}, {%4,%5,%6,%7}, {%8,%9}, {%0,%1,%2,%3};"
                 : "+f"(d[0]), "+f"(d[1]), "+f"(d[2]), "+f"(d[3])
                 : "r"(a[0]), "r"(a[1]), "r"(a[2]), "r"(a[3]), "r"(b0), "r"(b1));
}
__device__ __forceinline__ uint32_t pkh(float a, float b) {
    __half2 h = __floats2half2_rn(a, b);
    return *reinterpret_cast<uint32_t*>(&h);
}
__device__ __forceinline__ float ftanh(float x) {
    float e = __expf(2.0f * x);
    return 1.0f - __fdividef(2.0f, e + 1.0f);
}

// ---------------- SMEM layout (bytes) ----------------
#define PITCH    80
#define OFF_B    5120
#define BUFSZ    15360
#define NSTAGE   3
#define SM_QB    (NSTAGE * BUFSZ)     // 46080
#define SM_WS    (SM_QB + 4096)
#define SM_RED   (SM_WS + 4096)
#define SM_TOTAL (SM_RED + 1024)      // 55296 (x3 CTAs = 166 KB/SM)

// ---------------------------------------------------------------------------
// setup: blocks [0,1024) Wk->fp16; [1024,5120) qb; block 5120 zeroes counters
// ---------------------------------------------------------------------------
__global__ void setup_kernel(const float* __restrict__ query,
                             const float* __restrict__ Wq,
                             const float* __restrict__ bias,
                             const float* __restrict__ Wk) {
    if (blockIdx.x == 5120) {
        if (threadIdx.x < BATCH) {
            g_done_score[threadIdx.x] = 0;
            g_soft_flag[threadIdx.x]  = 0;
            g_ctx_done[threadIdx.x]   = 0;
        }
        if (threadIdx.x == 0) g_next = 0;
    } else if (blockIdx.x < 1024) {
        int i = (blockIdx.x * 256 + threadIdx.x) * 4;
        float4 w = *reinterpret_cast<const float4*>(Wk + i);
        *reinterpret_cast<uint2*>(g_wk + i) = make_uint2(pkh(w.x, w.y), pkh(w.z, w.w));
    } else {
        int w    = (((int)blockIdx.x - 1024) * 256 + (int)threadIdx.x) >> 5;
        int lane = threadIdx.x & 31;
        int b = w / HDIM;
        int o = w % HDIM;
        const float* wrow = Wq + (size_t)o * HDIM;
        const float* qrow = query + (size_t)b * HDIM;
        float s = 0.0f;
#pragma unroll 8
        for (int h = lane; h < HDIM; h += 32) s += wrow[h] * qrow[h];
#pragma unroll
        for (int off = 16; off; off >>= 1) s += __shfl_xor_sync(0xffffffffu, s, off);
        if (lane == 0) g_qb[w] = s + bias[o];
    }
}

// ---------------------------------------------------------------------------
// Persistent fused kernel: 444 CTAs pull jobs off a global counter.
//  [0,2048)      score tiles (b = j>>6, v0 = (j&63)*64)   — R13/R14 body
//  [2048,2080)   softmax per b (spin: 64 score tiles of b done)
//  [2080,2592)   context partials (b = k>>4, vs = k&15; spin: softmax b done)
//  [2592,2624)   context reduce per b (spin: 16 partials of b done)
// ---------------------------------------------------------------------------
__global__ void __launch_bounds__(256, 3)
fused_kernel(const float* __restrict__ key, const float* __restrict__ Ws,
             const float* __restrict__ value,
             float* __restrict__ attn_out, float* __restrict__ ctx_out) {
    extern __shared__ __align__(16) char smem[];
    __shared__ int s_job;
    __shared__ float red[256];
    const uint32_t sb = smem_u32(smem);
    const int tid  = threadIdx.x;
    const int lane = tid & 31;
    const int wid  = tid >> 5;

    for (;;) {
        __syncthreads();                         // quiesce smem before reuse
        if (tid == 0) s_job = atomicAdd(&g_next, 1);
        __syncthreads();
        const int js = s_job;
        if (js >= N_JOBS) return;

        if (js < N_SCORE) {
            // ================= score tile =================
            const int b  = js >> 6;
            const int v0 = (js & 63) * 64;
            const int wy = wid >> 2, wx = wid & 3;
            const size_t kbase = ((size_t)b * VLEN + v0) * HDIM;

            // convert this tile's 64x1024 key block to fp16
            {
                const float* kf = key + kbase;
                __half* kh = g_key16 + kbase;
#pragma unroll 4
                for (int it = 0; it < 32; it++) {
                    const int e = (tid + it * 256) * 8;
                    const float4 a = *reinterpret_cast<const float4*>(kf + e);
                    const float4 c = *reinterpret_cast<const float4*>(kf + e + 4);
                    __stcg(reinterpret_cast<uint4*>(kh + e),
                           make_uint4(pkh(a.x, a.y), pkh(a.z, a.w), pkh(c.x, c.y), pkh(c.z, c.w)));
                }
                __threadfence();
            }

            float* qbs = reinterpret_cast<float*>(smem + SM_QB);
            float* wss = reinterpret_cast<float*>(smem + SM_WS);
#pragma unroll
            for (int i = 0; i < 4; i++) {
                qbs[tid + i * 256] = g_qb[b * HDIM + tid + i * 256];
                wss[tid + i * 256] = Ws[tid + i * 256];
            }
            __syncthreads();

            const __half* keyb = g_key16 + kbase;
            const int arow = tid >> 2, aseg = tid & 3;
            const int brow = tid >> 1, bseg = (tid & 1) * 2;

            const uint32_t aoff  = (uint32_t)((lane & 15) * PITCH + (lane >> 4) * 16);
            const uint32_t Abase = sb + (uint32_t)(wy * 32 * PITCH) + aoff;
            const uint32_t Bbase = sb + OFF_B + (uint32_t)(wx * 32 * PITCH) + aoff;
            const uint32_t sa_a  = (uint32_t)(arow * PITCH + aseg * 16);
            const uint32_t sa_b0 = (uint32_t)(OFF_B + brow * PITCH + bseg * 16);
            const __half* kap = keyb + (size_t)arow * HDIM + aseg * 8;
            const __half* wbp = g_wk + (size_t)brow * HDIM + bseg * 8;

            float d[2][4][4];
#pragma unroll
            for (int mt = 0; mt < 2; mt++)
#pragma unroll
                for (int j = 0; j < 4; j++)
#pragma unroll
                    for (int q = 0; q < 4; q++) d[mt][j][q] = 0.0f;
            float part[4] = {0.f, 0.f, 0.f, 0.f};

            auto issue_b = [&](int n, int s) {
                const int oh = (n >> 5) * (128 * HDIM) + (n & 31) * 32;
                const uint32_t bb = sb + (uint32_t)s * BUFSZ;
                cp16(bb + sa_b0, wbp + oh);
                cp16(bb + sa_b0 + 16, wbp + oh + 8);
                CP_COMMIT();
            };
            auto a_addr = [&](int n) { return kap + (n & 31) * 32; };

            uint4 a0    = *reinterpret_cast<const uint4*>(a_addr(0));
            uint4 apend = *reinterpret_cast<const uint4*>(a_addr(1));
            issue_b(0, 0);
            issue_b(1, 1);
            *reinterpret_cast<uint4*>(smem + sa_a) = a0;

            int stage = 0;
            for (int gc = 0; gc < 256; gc++) {
                if (gc <= 254) { CP_WAIT(1); } else { CP_WAIT(0); }
                __syncthreads();

                if (gc <= 254) {
                    int s1 = stage + 1; if (s1 == NSTAGE) s1 = 0;
                    *reinterpret_cast<uint4*>(smem + (size_t)s1 * BUFSZ + sa_a) = apend;
                }
                if (gc <= 253) {
                    apend = *reinterpret_cast<const uint4*>(a_addr(gc + 2));
                    int ns = stage + 2; if (ns >= NSTAGE) ns -= NSTAGE;
                    issue_b(gc + 2, ns);
                }

                {
                    const uint32_t abuf = Abase + (uint32_t)stage * BUFSZ;
                    const uint32_t bbuf = Bbase + (uint32_t)stage * BUFSZ;
#pragma unroll
                    for (int ks = 0; ks < 2; ks++) {
                        uint32_t Bh[2][4];
#pragma unroll
                        for (int jj = 0; jj < 2; jj++)
                            ldsm4(Bh[jj], bbuf + jj * (16 * PITCH) + ks * 32);
                        uint32_t Ah[2][4];
#pragma unroll
                        for (int mt = 0; mt < 2; mt++)
                            ldsm4(Ah[mt], abuf + mt * (16 * PITCH) + ks * 32);
#pragma unroll
                        for (int mt = 0; mt < 2; mt++)
#pragma unroll
                            for (int jj = 0; jj < 2; jj++)
#pragma unroll
                                for (int h = 0; h < 2; h++)
                                    mma_f16(d[mt][jj * 2 + h], Ah[mt], Bh[jj][h], Bh[jj][2 + h]);
                    }
                }

                if ((gc & 31) == 31) {
                    const int o0 = (gc >> 5) * 128;
                    const int cb = o0 + wx * 32 + (lane & 3) * 2;
#pragma unroll
                    for (int mt = 0; mt < 2; mt++) {
#pragma unroll
                        for (int j = 0; j < 4; j++) {
                            const int o = cb + j * 8;
                            const float w0 = wss[o], w1 = wss[o + 1];
                            const float q0 = qbs[o], q1 = qbs[o + 1];
                            part[mt * 2 + 0] += w0 * ftanh(d[mt][j][0] + q0) + w1 * ftanh(d[mt][j][1] + q1);
                            part[mt * 2 + 1] += w0 * ftanh(d[mt][j][2] + q0) + w1 * ftanh(d[mt][j][3] + q1);
                            d[mt][j][0] = 0.0f; d[mt][j][1] = 0.0f;
                            d[mt][j][2] = 0.0f; d[mt][j][3] = 0.0f;
                        }
                    }
                }
                if (++stage == NSTAGE) stage = 0;
            }

#pragma unroll
            for (int i = 0; i < 4; i++) {
                part[i] += __shfl_xor_sync(0xffffffffu, part[i], 1);
                part[i] += __shfl_xor_sync(0xffffffffu, part[i], 2);
            }
            float* rd = reinterpret_cast<float*>(smem + SM_RED);
            if ((lane & 3) == 0) {
                const int r0 = wy * 32 + (lane >> 2);
#pragma unroll
                for (int mt = 0; mt < 2; mt++) {
                    rd[wx * 64 + r0 + mt * 16]     = part[mt * 2 + 0];
                    rd[wx * 64 + r0 + mt * 16 + 8] = part[mt * 2 + 1];
                }
            }
            __syncthreads();
            if (tid < 64) {
                const float s = rd[tid] + rd[64 + tid] + rd[128 + tid] + rd[192 + tid];
                g_score[b * VLEN + v0 + tid] = s;
            }
            __threadfence();
            __syncthreads();
            if (tid == 0) atomicAdd(&g_done_score[b], 1);

        } else if (js < J_CTX) {
            // ================= softmax for batch b =================
            const int b = js - J_SOFT;
            if (tid == 0) {
                while (atomicAdd(&g_done_score[b], 0) < 64) __nanosleep(200);
            }
            __syncthreads();
            __threadfence();

            const float* s = g_score + b * VLEN;
            float local[16];
            float mx = -1e30f;
#pragma unroll
            for (int i = 0; i < 16; i++) {
                local[i] = s[tid + i * 256];
                mx = fmaxf(mx, local[i]);
            }
            red[tid] = mx;
            __syncthreads();
            for (int o = 128; o; o >>= 1) {
                if (tid < o) red[tid] = fmaxf(red[tid], red[tid + o]);
                __syncthreads();
            }
            mx = red[0];
            __syncthreads();
            float sum = 0.0f;
#pragma unroll
            for (int i = 0; i < 16; i++) {
                local[i] = expf(local[i] - mx);
                sum += local[i];
            }
            red[tid] = sum;
            __syncthreads();
            for (int o = 128; o; o >>= 1) {
                if (tid < o) red[tid] += red[tid + o];
                __syncthreads();
            }
            const float inv = 1.0f / red[0];
#pragma unroll
            for (int i = 0; i < 16; i++) attn_out[b * VLEN + tid + i * 256] = local[i] * inv;

            __threadfence();
            __syncthreads();
            if (tid == 0) atomicExch(&g_soft_flag[b], 1);

        } else if (js < J_RED) {
            // ================= context partial (b, vs) =================
            const int k  = js - J_CTX;
            const int b  = k >> 4;
            const int vs = k & 15;
            if (tid == 0) {
                while (atomicAdd(&g_soft_flag[b], 0) == 0) __nanosleep(200);
            }
            __syncthreads();
            __threadfence();

            float* a_s = reinterpret_cast<float*>(smem);
            const int v0 = vs * 256;
            a_s[tid] = attn_out[b * VLEN + v0 + tid];
            __syncthreads();

            const int h = tid * 4;
            const float* vp = value + ((size_t)b * VLEN + v0) * HDIM + h;
            float ax = 0.f, ay = 0.f, az = 0.f, aw = 0.f;
            for (int v = 0; v < 256; v += 8) {
#pragma unroll
                for (int j = 0; j < 8; j++) {
                    const float4 x = *reinterpret_cast<const float4*>(vp + (size_t)(v + j) * HDIM);
                    const float a = a_s[v + j];
                    ax += a * x.x; ay += a * x.y; az += a * x.z; aw += a * x.w;
                }
            }
            *reinterpret_cast<float4*>(g_ctx_part + ((size_t)vs * BATCH + b) * HDIM + h) =
                make_float4(ax, ay, az, aw);
            __threadfence();
            __syncthreads();
            if (tid == 0) atomicAdd(&g_ctx_done[b], 1);

        } else {
            // ================= context reduce for batch b =================
            const int b = js - J_RED;
            if (tid == 0) {
                while (atomicAdd(&g_ctx_done[b], 0) < 16) __nanosleep(200);
            }
            __syncthreads();
            __threadfence();
#pragma unroll
            for (int r = 0; r < 4; r++) {
                const int h = tid + r * 256;
                float s = 0.0f;
#pragma unroll
                for (int vs = 0; vs < 16; vs++)
                    s += g_ctx_part[(size_t)vs * BATCH * HDIM + b * HDIM + h];
                ctx_out[b * HDIM + h] = s;
            }
        }
    }
}

// ---------------------------------------------------------------------------
// Launch. Inputs: query, key, value, Wq, Wk, bias, Ws, bs.
// Output: context (32*1024) then attn (32*4096).
// ---------------------------------------------------------------------------
extern "C" void kernel_launch(void* const* d_in, const int* in_sizes, int n_in,
                              void* d_out, int out_size) {
    const float* query = (const float*)d_in[0];
    const float* key   = (const float*)d_in[1];
    const float* value = (const float*)d_in[2];
    const float* Wq    = (const float*)d_in[3];
    const float* Wk    = (const float*)d_in[4];
    const float* bias  = (const float*)d_in[5];
    const float* Ws    = (const float*)d_in[6];

    float* out  = (float*)d_out;
    float* ctx  = out;                    // (B, 1, H)
    float* attn = out + BATCH * HDIM;     // (B, V)

    cudaFuncSetAttribute(fused_kernel, cudaFuncAttributeMaxDynamicSharedMemorySize, SM_TOTAL);

    setup_kernel<<<5121, 256>>>(query, Wq, bias, Wk);
    fused_kernel<<<GRID_P, 256, SM_TOTAL>>>(key, Ws, value, attn, ctx);
}